// round 3
// baseline (speedup 1.0000x reference)
#include <cuda_runtime.h>
#include <math.h>

#define CM 64      // d_model
#define DI 128     // d_inner
#define DS 16      // d_state
#define NPIX 14400
#define HWD 120
#define LPIX 576
#define NCHUNK 100
#define CLEN 144

// ---------------- static scratch ----------------
__device__ float g_xn[CM*NPIX];
__device__ float g_xzT[2*2*DI*NPIX];   // [dir][256][tok]; rows 0..127 xh, 128..255 z
__device__ float g_u [2*DI*NPIX];
__device__ float g_dl[2*DI*NPIX];
__device__ float g_Bmb[2*NPIX*DS];     // [dir][tok][n]
__device__ float g_Cmb[2*NPIX*DS];
__device__ float g_gb0[DI*NPIX];
__device__ float g_gb1[DI*NPIX];
__device__ float g_yo [CM*NPIX];
__device__ float g_curA[CM*NPIX];
__device__ float g_curB[CM*NPIX];
__device__ float g_bufA[CM*NPIX];
__device__ float g_nf [4*CM*NPIX];
__device__ float g_t1 [2*CM*NPIX];
__device__ float g_t2 [CM*NPIX];
__device__ float g_P  [2*DI*DS*NCHUNK];
__device__ float g_He [2*DI*DS*NCHUNK];
__device__ float g_Hsb[2*DI*DS*NCHUNK];
__device__ float g_hub[2*CM];

// ---------------- LayerNorm + gather ----------------
__global__ void k_ln(const float* __restrict__ img, const float* __restrict__ g,
                     const float* __restrict__ b, int pixelMode)
{
    int tok = blockIdx.x*blockDim.x + threadIdx.x;
    if (tok >= NPIX) return;
    int p;
    if (pixelMode){
        int sq = tok/LPIX, l = tok%LPIX;
        int nh = l/24, nw = l%24, pi = sq/5, pj = sq%5;
        p = (nh*5+pi)*HWD + (nw*5+pj);
    } else p = tok;
    float xl[CM];
    float s = 0.f;
#pragma unroll
    for (int c=0;c<CM;c++){ xl[c] = img[(size_t)c*NPIX+p]; s += xl[c]; }
    float m = s*(1.f/CM), v = 0.f;
#pragma unroll
    for (int c=0;c<CM;c++){ float d = xl[c]-m; v += d*d; }
    float rs = rsqrtf(v*(1.f/CM) + 1e-5f);
#pragma unroll
    for (int c=0;c<CM;c++) g_xn[(size_t)c*NPIX+tok] = (xl[c]-m)*rs*g[c] + b[c];
}

// ---------------- GEMM: C[n][m] = sum_k W[n][k]*(X+X2)[k][m]; dims %64==0 -----
__global__ __launch_bounds__(256) void k_gemm(const float* __restrict__ X,
        const float* __restrict__ X2,
        const float* __restrict__ W, float* __restrict__ C,
        int M, int N, int K, int rev)
{
    __shared__ __align__(16) float Xs[64*64];
    __shared__ __align__(16) float Ws[64*64];
    int t0 = blockIdx.x*64, n0 = blockIdx.y*64;
    int tid = threadIdx.x;
    int tg = tid & 15, eo = tid >> 4;
    float acc[4][4];
#pragma unroll
    for (int j=0;j<4;j++){ acc[j][0]=0.f; acc[j][1]=0.f; acc[j][2]=0.f; acc[j][3]=0.f; }
    for (int k0=0;k0<K;k0+=64){
#pragma unroll
        for (int i=tid;i<4096;i+=256){
            int kk=i>>6, tt=i&63;
            size_t idx = (size_t)(k0+kk)*M + t0+tt;
            float v = X[idx];
            if (X2) v += X2[idx];
            Xs[i] = v;
        }
#pragma unroll
        for (int i=tid;i<4096;i+=256){
            int e=i>>6, kk=i&63;
            Ws[i] = W[(size_t)(n0+e)*K + k0+kk];
        }
        __syncthreads();
#pragma unroll 16
        for (int kk=0;kk<64;kk++){
            float4 xv = *(const float4*)&Xs[kk*64 + tg*4];
#pragma unroll
            for (int j=0;j<4;j++){
                float wv = Ws[(eo*4+j)*64 + kk];
                acc[j][0] += xv.x*wv; acc[j][1] += xv.y*wv;
                acc[j][2] += xv.z*wv; acc[j][3] += xv.w*wv;
            }
        }
        __syncthreads();
    }
#pragma unroll
    for (int j=0;j<4;j++){
        size_t row = (size_t)(n0+eo*4+j)*M;
        if (!rev){
            float4 o = make_float4(acc[j][0],acc[j][1],acc[j][2],acc[j][3]);
            *(float4*)&C[row + t0 + tg*4] = o;
        } else {
#pragma unroll
            for (int mj=0;mj<4;mj++) C[row + (M-1-(t0+tg*4+mj))] = acc[j][mj];
        }
    }
}

// ---------------- conv + silu -> u (fully parallel) ----------------
__global__ void k_convu(const float* __restrict__ conv_w, const float* __restrict__ conv_b,
                        int Lseq)
{
    int tok = blockIdx.x*blockDim.x + threadIdx.x;
    if (tok >= NPIX) return;
    int ch = blockIdx.y, dir = blockIdx.z;
    int l = tok % Lseq;
    const float* row = g_xzT + ((size_t)dir*2*DI + ch)*NPIX;
    const float* cw = conv_w + ((size_t)dir*DI + ch)*4;
    float acc = conv_b[dir*DI + ch];
    if (dir==0){
#pragma unroll
        for (int j=0;j<4;j++) if (l>=j) acc += row[tok-j]*cw[3-j];
    } else {
#pragma unroll
        for (int j=0;j<4;j++) if (l+j<Lseq) acc += row[tok+j]*cw[3-j];
    }
    g_u[((size_t)dir*DI+ch)*NPIX + tok] = acc/(1.f+__expf(-acc));
}

// ------- xproj (36x128 @ u) + dt-proj + softplus + B/C scatter ---------------
// 4 threads per token (K split 4x32), butterfly reduce, distributed epilogue.
__global__ __launch_bounds__(256) void k_xproj(const float* __restrict__ xproj_w,
    const float* __restrict__ dt_w, const float* __restrict__ dt_b)
{
    int dir = blockIdx.y;
    __shared__ float xs[36*DI];
    __shared__ float dws[DI*4];
    __shared__ float dbs[DI];
    {
        const float* xp = xproj_w + (size_t)dir*36*DI;
        const float* dw = dt_w + (size_t)dir*DI*4;
        const float* db = dt_b + dir*DI;
        for (int t=threadIdx.x;t<36*DI;t+=blockDim.x) xs[t]=xp[t];
        for (int t=threadIdx.x;t<DI*4;t+=blockDim.x) dws[t]=dw[t];
        for (int t=threadIdx.x;t<DI;t+=blockDim.x) dbs[t]=db[t];
    }
    __syncthreads();
    int lane = threadIdx.x & 31;
    int warp = threadIdx.x >> 5;
    int kg = lane >> 3;            // 0..3 : K-split group
    int tl = lane & 7;             // token within group of 8
    int tok = blockIdx.x*64 + warp*8 + tl;
    const float* up = g_u + (size_t)dir*DI*NPIX;
    float dbl[36];
#pragma unroll
    for (int j=0;j<36;j++) dbl[j]=0.f;
    for (int c=0;c<32;c++){
        int ch = kg*32 + c;
        float uu = up[(size_t)ch*NPIX + tok];
#pragma unroll
        for (int j=0;j<36;j++) dbl[j] += xs[j*DI+ch]*uu;
    }
#pragma unroll
    for (int j=0;j<36;j++){
        dbl[j] += __shfl_xor_sync(0xffffffffu, dbl[j], 8);
        dbl[j] += __shfl_xor_sync(0xffffffffu, dbl[j], 16);
    }
    // dt-proj + softplus: each kg lane handles 32 channels
    for (int c=0;c<32;c++){
        int ch = kg*32 + c;
        float t = dbs[ch] + dws[ch*4+0]*dbl[0] + dws[ch*4+1]*dbl[1]
                + dws[ch*4+2]*dbl[2] + dws[ch*4+3]*dbl[3];
        t = (t>20.f)? t : log1pf(__expf(t));
        g_dl[((size_t)dir*DI+ch)*NPIX + tok] = t;
    }
    size_t bidx = ((size_t)dir*NPIX+tok)*DS;
    if (kg<2){
#pragma unroll
        for (int i=0;i<8;i++) g_Bmb[bidx + kg*8 + i] = dbl[4 + kg*8 + i];
    } else {
#pragma unroll
        for (int i=0;i<8;i++) g_Cmb[bidx + (kg-2)*8 + i] = dbl[20 + (kg-2)*8 + i];
    }
}

// ---------------- pixel scan + fused gate ----------------
__global__ void k_scan_pix(const float* __restrict__ Alog, const float* __restrict__ Dv)
{
    int dir = blockIdx.z, seq = blockIdx.y;
    int n = threadIdx.x & 15;
    int d = blockIdx.x*16 + (threadIdx.x>>4);
    float Aa = -__expf(Alog[((size_t)dir*DI+d)*DS+n]);
    float Dd = Dv[dir*DI+d];
    const float* dlp = g_dl + ((size_t)dir*DI+d)*NPIX;
    const float* up  = g_u  + ((size_t)dir*DI+d)*NPIX;
    const float* Bp  = g_Bmb + (size_t)dir*NPIX*DS;
    const float* Cp  = g_Cmb + (size_t)dir*NPIX*DS;
    const float* zp  = g_xzT + (((size_t)dir*2+1)*DI+d)*NPIX;
    float* gp = (dir ? g_gb1 : g_gb0) + (size_t)d*NPIX;
    float h = 0.f;
    int s0 = seq*LPIX;
    for (int t=0;t<LPIX;t++){
        int tok = s0 + (dir ? (LPIX-1-t) : t);
        float dd = dlp[tok];
        float uu = up[tok];
        float a = __expf(dd*Aa);
        h = h*a + dd*uu*Bp[(size_t)tok*DS+n];
        float cc = h*Cp[(size_t)tok*DS+n];
        cc += __shfl_xor_sync(0xffffffffu, cc, 8);
        cc += __shfl_xor_sync(0xffffffffu, cc, 4);
        cc += __shfl_xor_sync(0xffffffffu, cc, 2);
        cc += __shfl_xor_sync(0xffffffffu, cc, 1);
        if (n==0){
            float z = zp[tok];
            gp[tok] = (cc + uu*Dd) * (z/(1.f+__expf(-z)));
        }
    }
}

// ---------------- window scan: 3-phase chunked linear recurrence -------------
__global__ void k_scan_win1(const float* __restrict__ Alog)
{
    int dir = blockIdx.z, chunk = blockIdx.y;
    int n = threadIdx.x & 15;
    int d = blockIdx.x*16 + (threadIdx.x>>4);
    float Aa = -__expf(Alog[((size_t)dir*DI+d)*DS+n]);
    const float* dlp = g_dl + ((size_t)dir*DI+d)*NPIX;
    const float* up  = g_u  + ((size_t)dir*DI+d)*NPIX;
    const float* Bp  = g_Bmb + (size_t)dir*NPIX*DS;
    float h = 0.f, p = 1.f;
    int s0 = chunk*CLEN;
    for (int t=0;t<CLEN;t++){
        int s = s0+t;
        int tok = dir ? (NPIX-1-s) : s;
        float dd = dlp[tok];
        float a = __expf(dd*Aa);
        h = h*a + dd*up[tok]*Bp[(size_t)tok*DS+n];
        p *= a;
    }
    size_t idx = (((size_t)dir*DI+d)*DS+n)*NCHUNK + chunk;
    g_P[idx]=p; g_He[idx]=h;
}

__global__ void k_scan_win2()
{
    int idx = blockIdx.x*blockDim.x + threadIdx.x;
    if (idx >= 2*DI*DS) return;
    size_t base = (size_t)idx*NCHUNK;
    float h = 0.f;
    for (int c=0;c<NCHUNK;c++){
        g_Hsb[base+c] = h;
        h = g_He[base+c] + g_P[base+c]*h;
    }
}

__global__ void k_scan_win3(const float* __restrict__ Alog, const float* __restrict__ Dv)
{
    int dir = blockIdx.z, chunk = blockIdx.y;
    int n = threadIdx.x & 15;
    int d = blockIdx.x*16 + (threadIdx.x>>4);
    float Aa = -__expf(Alog[((size_t)dir*DI+d)*DS+n]);
    float Dd = Dv[dir*DI+d];
    const float* dlp = g_dl + ((size_t)dir*DI+d)*NPIX;
    const float* up  = g_u  + ((size_t)dir*DI+d)*NPIX;
    const float* Bp  = g_Bmb + (size_t)dir*NPIX*DS;
    const float* Cp  = g_Cmb + (size_t)dir*NPIX*DS;
    const float* zp  = g_xzT + (((size_t)dir*2+1)*DI+d)*NPIX;
    float* gp = (dir ? g_gb1 : g_gb0) + (size_t)d*NPIX;
    float h = g_Hsb[(((size_t)dir*DI+d)*DS+n)*NCHUNK + chunk];
    int s0 = chunk*CLEN;
    for (int t=0;t<CLEN;t++){
        int s = s0+t;
        int tok = dir ? (NPIX-1-s) : s;
        float dd = dlp[tok];
        float uu = up[tok];
        float a = __expf(dd*Aa);
        h = h*a + dd*uu*Bp[(size_t)tok*DS+n];
        float cc = h*Cp[(size_t)tok*DS+n];
        cc += __shfl_xor_sync(0xffffffffu, cc, 8);
        cc += __shfl_xor_sync(0xffffffffu, cc, 4);
        cc += __shfl_xor_sync(0xffffffffu, cc, 2);
        cc += __shfl_xor_sync(0xffffffffu, cc, 1);
        if (n==0){
            float z = zp[tok];
            gp[tok] = (cc + uu*Dd) * (z/(1.f+__expf(-z)));
        }
    }
}

// ---------------- residual helpers ----------------
__global__ void k_addpix(const float* __restrict__ base, float* __restrict__ outb)
{
    int p = blockIdx.x*blockDim.x + threadIdx.x;
    if (p >= NPIX) return;
    int c = blockIdx.y;
    int h = p/HWD, w = p%HWD;
    int nh=h/5, pi=h%5, nw=w/5, pj=w%5;
    int tok = (pi*5+pj)*LPIX + nh*24+nw;
    outb[(size_t)c*NPIX+p] = base[(size_t)c*NPIX+p] + g_yo[(size_t)c*NPIX+tok];
}

__global__ void k_add3(float* __restrict__ cur, const float* __restrict__ buf)
{
    int p = blockIdx.x*blockDim.x + threadIdx.x;
    if (p >= NPIX) return;
    int c = blockIdx.y;
    size_t i = (size_t)c*NPIX+p;
    cur[i] = cur[i] + buf[i] + g_yo[i];
}

__global__ void k_transpose(const float* __restrict__ src, float* __restrict__ dst)
{
    int p = blockIdx.x*blockDim.x + threadIdx.x;
    if (p >= NPIX) return;
    int c = blockIdx.y;
    int h = p/HWD, w = p%HWD;
    dst[(size_t)c*NPIX+p] = src[(size_t)c*NPIX + w*HWD + h];
}

// ---------------- GCN hub handling ----------------
__global__ void k_hubmean(const float* __restrict__ X)
{
    int f = blockIdx.x;
    __shared__ float sm[256];
    float s = 0.f;
    for (int k=threadIdx.x;k<450;k+=256) s += X[(size_t)f*NPIX + k*32];
    sm[threadIdx.x]=s; __syncthreads();
    for (int st=128;st>0;st>>=1){
        if (threadIdx.x<st) sm[threadIdx.x]+=sm[threadIdx.x+st];
        __syncthreads();
    }
    if (threadIdx.x==0) g_hub[f]=sm[0]*(1.f/450.f);
}

__global__ void k_hubapply(float* __restrict__ X, const float* __restrict__ bias, int doRelu)
{
    int m = blockIdx.x*blockDim.x + threadIdx.x;
    if (m >= NPIX) return;
    int f = blockIdx.y;
    float v = X[(size_t)f*NPIX+m];
    if ((m & 31) == 0) v = g_hub[f];
    v += bias[f];
    if (doRelu) v = fmaxf(v, 0.f);
    X[(size_t)f*NPIX+m] = v;
}

__global__ void k_final(const float* __restrict__ x, float* __restrict__ out)
{
    int p = blockIdx.x*blockDim.x + threadIdx.x;
    if (p >= NPIX) return;
    int c = blockIdx.y;
    int h = p/HWD, w = p%HWD;
    out[(size_t)c*NPIX+p] = x[(size_t)c*NPIX+p] + g_curA[(size_t)c*NPIX+p]
        + g_curB[(size_t)c*NPIX + w*HWD + h] + g_t2[(size_t)c*NPIX+p];
}

// ---------------- host driver ----------------
static void mamba_inv(const float* img, int pixelMode, int i,
    const float* in_w_all, const float* conv_w_all, const float* conv_b_all,
    const float* xproj_all, const float* dt_w_all, const float* dt_b_all,
    const float* Alog_all, const float* D_all,
    const float* lng, const float* lnb,
    float* p_xn, float* p_xzT)
{
    const float* in_w   = in_w_all   + (size_t)i*2*2*DI*CM;
    const float* conv_w = conv_w_all + (size_t)i*2*DI*4;
    const float* conv_b = conv_b_all + (size_t)i*2*DI;
    const float* xproj  = xproj_all  + (size_t)i*2*36*DI;
    const float* dt_w   = dt_w_all   + (size_t)i*2*DI*4;
    const float* dt_b   = dt_b_all   + (size_t)i*2*DI;
    const float* Alog   = Alog_all   + (size_t)i*2*DI*DS;
    const float* Dv     = D_all      + (size_t)i*2*DI;
    const float* lg     = lng + (size_t)i*CM;
    const float* lb     = lnb + (size_t)i*CM;

    k_ln<<<113,128>>>(img, lg, lb, pixelMode);
    // both directions in one launch: W is [2][256][64] = N=512 rows
    k_gemm<<<dim3(225,8),256>>>(p_xn, nullptr, in_w, p_xzT, NPIX, 4*DI, CM, 0);
    k_convu<<<dim3(57,DI,2),256>>>(conv_w, conv_b, pixelMode?LPIX:NPIX);
    k_xproj<<<dim3(225,2),256>>>(xproj, dt_w, dt_b);
    if (pixelMode){
        k_scan_pix<<<dim3(8,25,2),256>>>(Alog, Dv);
    } else {
        k_scan_win1<<<dim3(8,NCHUNK,2),256>>>(Alog);
        k_scan_win2<<<4,1024>>>();
        k_scan_win3<<<dim3(8,NCHUNK,2),256>>>(Alog, Dv);
    }
}

extern "C" void kernel_launch(void* const* d_in, const int* in_sizes, int n_in,
                              void* d_out, int out_size)
{
    const float* A[28];
    if (in_sizes[9] == 256){
        const int map[28] = {0,1,2,3,4,5,6,7,8, 11,12,13,14,15,16,17,18,
                             9,10, 19,20, 21,22,23,24,25,26,27};
        for (int k=0;k<28;k++) A[k]=(const float*)d_in[map[k]];
    } else {
        for (int k=0;k<28;k++) A[k]=(const float*)d_in[k];
    }
    const float* x = A[0];
    float *p_xn,*p_xzT,*p_gb0,*p_gb1,*p_yo,*p_curA,*p_curB,*p_bufA,*p_nf,*p_t1,*p_t2;
    cudaGetSymbolAddress((void**)&p_xn,  g_xn);
    cudaGetSymbolAddress((void**)&p_xzT, g_xzT);
    cudaGetSymbolAddress((void**)&p_gb0, g_gb0);
    cudaGetSymbolAddress((void**)&p_gb1, g_gb1);
    cudaGetSymbolAddress((void**)&p_yo,  g_yo);
    cudaGetSymbolAddress((void**)&p_curA,g_curA);
    cudaGetSymbolAddress((void**)&p_curB,g_curB);
    cudaGetSymbolAddress((void**)&p_bufA,g_bufA);
    cudaGetSymbolAddress((void**)&p_nf,  g_nf);
    cudaGetSymbolAddress((void**)&p_t1,  g_t1);
    cudaGetSymbolAddress((void**)&p_t2,  g_t2);

    auto run_branch = [&](float* cur, int base, float* nfx, float* nfy){
        for (int s=0;s<2;s++){
            int i = base+s;
            // pixel mamba
            mamba_inv(cur, 1, i, A[1],A[2],A[3],A[4],A[5],A[6],A[7],A[8],
                      A[17],A[18], p_xn, p_xzT);
            k_gemm<<<dim3(225,1),256>>>(p_gb0, p_gb1, A[21] + (size_t)i*CM*DI, p_yo, NPIX, CM, DI, 0);
            k_addpix<<<dim3(113,CM),128>>>(cur, p_bufA);     // buf = cur + pixel residual
            // window mamba
            mamba_inv(p_bufA, 0, i, A[9],A[10],A[11],A[12],A[13],A[14],A[15],A[16],
                      A[19],A[20], p_xn, p_xzT);
            k_gemm<<<dim3(225,1),256>>>(p_gb0, p_gb1, A[22] + (size_t)i*CM*DI, p_yo, NPIX, CM, DI, 0);
            if (s==1){
                k_gemm<<<dim3(225,1),256>>>(p_gb0, nullptr, A[22] + (size_t)i*CM*DI, nfx, NPIX, CM, DI, 0);
                k_gemm<<<dim3(225,1),256>>>(p_gb1, nullptr, A[23] + (size_t)i*CM*DI, nfy, NPIX, CM, DI, 1);
            }
            k_add3<<<dim3(113,CM),128>>>(cur, p_bufA);       // cur += buf + window residual
        }
    };

    // branch 0 (original orientation)
    cudaMemcpyAsync(p_curA, x, sizeof(float)*CM*NPIX, cudaMemcpyDeviceToDevice);
    run_branch(p_curA, 0, p_nf + 0*(size_t)CM*NPIX, p_nf + 1*(size_t)CM*NPIX);

    // branch 1 (transposed orientation)
    k_transpose<<<dim3(113,CM),128>>>(x, p_curB);
    run_branch(p_curB, 2, p_nf + 2*(size_t)CM*NPIX, p_nf + 3*(size_t)CM*NPIX);

    // GCN: layer 1 (256 -> 128), hub substitution, bias, relu
    k_gemm<<<dim3(225,2),256>>>(p_nf, nullptr, A[24], p_t1, NPIX, 2*CM, 4*CM, 0);
    k_hubmean<<<2*CM,256>>>(p_t1);
    k_hubapply<<<dim3(113,2*CM),128>>>(p_t1, A[25], 1);
    // layer 2 (128 -> 64)
    k_gemm<<<dim3(225,1),256>>>(p_t1, nullptr, A[26], p_t2, NPIX, CM, 2*CM, 0);
    k_hubmean<<<CM,256>>>(p_t2);
    k_hubapply<<<dim3(113,CM),128>>>(p_t2, A[27], 0);

    // final: gcn + old + lastx + lastx_T^T
    k_final<<<dim3(113,CM),128>>>(x, (float*)d_out);
}

// round 4
// speedup vs baseline: 1.0929x; 1.0929x over previous
#include <cuda_runtime.h>
#include <math.h>

#define CM 64      // d_model
#define DI 128     // d_inner
#define DS 16      // d_state
#define NPIX 14400
#define HWD 120
#define LPIX 576
#define NCHUNK 100
#define CLEN 144

// ---------------- static scratch ----------------
__device__ float g_xn[CM*NPIX];
__device__ float g_xzT[2*2*DI*NPIX];   // [dir][256][tok]; rows 0..127 xh, 128..255 z
__device__ float g_u [2*DI*NPIX];
__device__ float g_dl[2*DI*NPIX];
__device__ float g_dbl[2*64*NPIX];     // xproj output, rows 0..35 valid (pad to 64)
__device__ float g_Bmb[2*NPIX*DS];     // [dir][tok][n]
__device__ float g_Cmb[2*NPIX*DS];
__device__ float g_gb0[DI*NPIX];
__device__ float g_gb1[DI*NPIX];
__device__ float g_yo [CM*NPIX];
__device__ float g_curA[CM*NPIX];
__device__ float g_curB[CM*NPIX];
__device__ float g_bufA[CM*NPIX];
__device__ float g_nf [4*CM*NPIX];
__device__ float g_t1 [2*CM*NPIX];
__device__ float g_t2 [CM*NPIX];
__device__ float g_P  [2*DI*DS*NCHUNK];
__device__ float g_He [2*DI*DS*NCHUNK];
__device__ float g_Hsb[2*DI*DS*NCHUNK];
__device__ float g_hub[2*CM];

// ---------------- LayerNorm + gather ----------------
__global__ void k_ln(const float* __restrict__ img, const float* __restrict__ g,
                     const float* __restrict__ b, int pixelMode)
{
    int tok = blockIdx.x*blockDim.x + threadIdx.x;
    if (tok >= NPIX) return;
    int p;
    if (pixelMode){
        int sq = tok/LPIX, l = tok%LPIX;
        int nh = l/24, nw = l%24, pi = sq/5, pj = sq%5;
        p = (nh*5+pi)*HWD + (nw*5+pj);
    } else p = tok;
    float xl[CM];
    float s = 0.f;
#pragma unroll
    for (int c=0;c<CM;c++){ xl[c] = img[(size_t)c*NPIX+p]; s += xl[c]; }
    float m = s*(1.f/CM), v = 0.f;
#pragma unroll
    for (int c=0;c<CM;c++){ float d = xl[c]-m; v += d*d; }
    float rs = rsqrtf(v*(1.f/CM) + 1e-5f);
#pragma unroll
    for (int c=0;c<CM;c++) g_xn[(size_t)c*NPIX+tok] = (xl[c]-m)*rs*g[c] + b[c];
}

// --------- GEMM2: C[cbase+n][m] = sum_k W[wbase+n][k]*(X+X2)[xbase+k][m] ------
// BM=64 tokens, BN=16*TN rows, BK=32. wbase=y*WS, cbase=y*CS, xbase=y*XS.
// Rows n with n>=NW read W as zero (padding support).
template<int TN>
__global__ __launch_bounds__(256) void k_gemm2(const float* __restrict__ X,
        const float* __restrict__ X2, const float* __restrict__ W,
        float* __restrict__ C, int M, int K, int NW, int WS, int CS, int XS, int rev)
{
    constexpr int BN = 16*TN;
    __shared__ __align__(16) float Xs[32][64];
    __shared__ float Ws[BN][33];
    int t0 = blockIdx.x*64;
    int wbase = blockIdx.y*WS;
    int cbase = blockIdx.y*CS;
    int xbase = blockIdx.y*XS;
    int tid = threadIdx.x;
    int tg = tid & 15, eg = tid >> 4;
    float acc[TN][4];
#pragma unroll
    for (int j=0;j<TN;j++){ acc[j][0]=0.f; acc[j][1]=0.f; acc[j][2]=0.f; acc[j][3]=0.f; }
    for (int k0=0;k0<K;k0+=32){
#pragma unroll
        for (int r=0;r<2;r++){
            int i = tid + r*256;
            int kk = i>>4, tt = (i&15)*4;
            size_t gidx = (size_t)(xbase+k0+kk)*M + t0+tt;
            float4 v = *(const float4*)&X[gidx];
            if (X2){
                float4 w = *(const float4*)&X2[gidx];
                v.x+=w.x; v.y+=w.y; v.z+=w.z; v.w+=w.w;
            }
            *(float4*)&Xs[kk][tt] = v;
        }
#pragma unroll
        for (int r=0;r<BN/32;r++){
            int i = tid + r*256;
            int e = i>>3, kkb = (i&7)*4;
            float4 v = make_float4(0.f,0.f,0.f,0.f);
            if (e < NW) v = *(const float4*)&W[(size_t)(wbase+e)*K + k0+kkb];
            Ws[e][kkb+0]=v.x; Ws[e][kkb+1]=v.y; Ws[e][kkb+2]=v.z; Ws[e][kkb+3]=v.w;
        }
        __syncthreads();
#pragma unroll 8
        for (int kk=0;kk<32;kk++){
            float4 xv = *(const float4*)&Xs[kk][tg*4];
#pragma unroll
            for (int j=0;j<TN;j++){
                float wv = Ws[eg*TN+j][kk];
                acc[j][0] += xv.x*wv; acc[j][1] += xv.y*wv;
                acc[j][2] += xv.z*wv; acc[j][3] += xv.w*wv;
            }
        }
        __syncthreads();
    }
#pragma unroll
    for (int j=0;j<TN;j++){
        size_t row = (size_t)(cbase + eg*TN + j)*M;
        if (!rev){
            float4 o = make_float4(acc[j][0],acc[j][1],acc[j][2],acc[j][3]);
            *(float4*)&C[row + t0 + tg*4] = o;
        } else {
#pragma unroll
            for (int mj=0;mj<4;mj++) C[row + (M-1-(t0+tg*4+mj))] = acc[j][mj];
        }
    }
}

// ---------------- conv + silu -> u (fully parallel) ----------------
__global__ void k_convu(const float* __restrict__ conv_w, const float* __restrict__ conv_b,
                        int Lseq)
{
    int tok = blockIdx.x*blockDim.x + threadIdx.x;
    if (tok >= NPIX) return;
    int ch = blockIdx.y, dir = blockIdx.z;
    int l = tok % Lseq;
    const float* row = g_xzT + ((size_t)dir*2*DI + ch)*NPIX;
    const float* cw = conv_w + ((size_t)dir*DI + ch)*4;
    float acc = conv_b[dir*DI + ch];
    if (dir==0){
#pragma unroll
        for (int j=0;j<4;j++) if (l>=j) acc += row[tok-j]*cw[3-j];
    } else {
#pragma unroll
        for (int j=0;j<4;j++) if (l+j<Lseq) acc += row[tok+j]*cw[3-j];
    }
    g_u[((size_t)dir*DI+ch)*NPIX + tok] = acc/(1.f+__expf(-acc));
}

// --------- dt-proj + softplus + B/C pack from g_dbl rows ----------
__global__ __launch_bounds__(256) void k_dtbc(const float* __restrict__ dt_w,
    const float* __restrict__ dt_b)
{
    int dir = blockIdx.y;
    __shared__ float dw[4][DI];
    __shared__ float db[DI];
    for (int t=threadIdx.x; t<DI*4; t+=blockDim.x)
        dw[t&3][t>>2] = dt_w[(size_t)dir*DI*4 + t];
    for (int t=threadIdx.x; t<DI; t+=blockDim.x) db[t] = dt_b[dir*DI + t];
    __syncthreads();
    int tok = blockIdx.x*blockDim.x + threadIdx.x;
    if (tok >= NPIX) return;
    const float* dbl = g_dbl + (size_t)dir*64*NPIX;
    float d0 = dbl[0*NPIX+tok], d1 = dbl[1*NPIX+tok];
    float d2 = dbl[2*NPIX+tok], d3 = dbl[3*NPIX+tok];
#pragma unroll 8
    for (int ch=0; ch<DI; ch++){
        float t = db[ch] + dw[0][ch]*d0 + dw[1][ch]*d1 + dw[2][ch]*d2 + dw[3][ch]*d3;
        t = (t>20.f)? t : log1pf(__expf(t));
        g_dl[((size_t)dir*DI+ch)*NPIX + tok] = t;
    }
    size_t bo = ((size_t)dir*NPIX + tok)*DS;
#pragma unroll
    for (int q=0;q<4;q++){
        float4 vb = make_float4(dbl[(4+q*4+0)*NPIX+tok], dbl[(4+q*4+1)*NPIX+tok],
                                dbl[(4+q*4+2)*NPIX+tok], dbl[(4+q*4+3)*NPIX+tok]);
        *(float4*)&g_Bmb[bo + q*4] = vb;
        float4 vc = make_float4(dbl[(20+q*4+0)*NPIX+tok], dbl[(20+q*4+1)*NPIX+tok],
                                dbl[(20+q*4+2)*NPIX+tok], dbl[(20+q*4+3)*NPIX+tok]);
        *(float4*)&g_Cmb[bo + q*4] = vc;
    }
}

// ---------------- pixel scan + fused gate ----------------
__global__ void k_scan_pix(const float* __restrict__ Alog, const float* __restrict__ Dv)
{
    int dir = blockIdx.z, seq = blockIdx.y;
    int n = threadIdx.x & 15;
    int d = blockIdx.x*16 + (threadIdx.x>>4);
    float Aa = -__expf(Alog[((size_t)dir*DI+d)*DS+n]);
    float Dd = Dv[dir*DI+d];
    const float* dlp = g_dl + ((size_t)dir*DI+d)*NPIX;
    const float* up  = g_u  + ((size_t)dir*DI+d)*NPIX;
    const float* Bp  = g_Bmb + (size_t)dir*NPIX*DS;
    const float* Cp  = g_Cmb + (size_t)dir*NPIX*DS;
    const float* zp  = g_xzT + (((size_t)dir*2+1)*DI+d)*NPIX;
    float* gp = (dir ? g_gb1 : g_gb0) + (size_t)d*NPIX;
    float h = 0.f;
    int s0 = seq*LPIX;
    for (int t=0;t<LPIX;t++){
        int tok = s0 + (dir ? (LPIX-1-t) : t);
        float dd = dlp[tok];
        float uu = up[tok];
        float a = __expf(dd*Aa);
        h = h*a + dd*uu*Bp[(size_t)tok*DS+n];
        float cc = h*Cp[(size_t)tok*DS+n];
        cc += __shfl_xor_sync(0xffffffffu, cc, 8);
        cc += __shfl_xor_sync(0xffffffffu, cc, 4);
        cc += __shfl_xor_sync(0xffffffffu, cc, 2);
        cc += __shfl_xor_sync(0xffffffffu, cc, 1);
        if (n==0){
            float z = zp[tok];
            gp[tok] = (cc + uu*Dd) * (z/(1.f+__expf(-z)));
        }
    }
}

// ---------------- window scan: 3-phase chunked linear recurrence -------------
__global__ void k_scan_win1(const float* __restrict__ Alog)
{
    int dir = blockIdx.z, chunk = blockIdx.y;
    int n = threadIdx.x & 15;
    int d = blockIdx.x*16 + (threadIdx.x>>4);
    float Aa = -__expf(Alog[((size_t)dir*DI+d)*DS+n]);
    const float* dlp = g_dl + ((size_t)dir*DI+d)*NPIX;
    const float* up  = g_u  + ((size_t)dir*DI+d)*NPIX;
    const float* Bp  = g_Bmb + (size_t)dir*NPIX*DS;
    float h = 0.f, p = 1.f;
    int s0 = chunk*CLEN;
    for (int t=0;t<CLEN;t++){
        int s = s0+t;
        int tok = dir ? (NPIX-1-s) : s;
        float dd = dlp[tok];
        float a = __expf(dd*Aa);
        h = h*a + dd*up[tok]*Bp[(size_t)tok*DS+n];
        p *= a;
    }
    size_t idx = (((size_t)dir*DI+d)*DS+n)*NCHUNK + chunk;
    g_P[idx]=p; g_He[idx]=h;
}

__global__ void k_scan_win2()
{
    int idx = blockIdx.x*blockDim.x + threadIdx.x;
    if (idx >= 2*DI*DS) return;
    size_t base = (size_t)idx*NCHUNK;
    float h = 0.f;
    for (int c=0;c<NCHUNK;c++){
        g_Hsb[base+c] = h;
        h = g_He[base+c] + g_P[base+c]*h;
    }
}

__global__ void k_scan_win3(const float* __restrict__ Alog, const float* __restrict__ Dv)
{
    int dir = blockIdx.z, chunk = blockIdx.y;
    int n = threadIdx.x & 15;
    int d = blockIdx.x*16 + (threadIdx.x>>4);
    float Aa = -__expf(Alog[((size_t)dir*DI+d)*DS+n]);
    float Dd = Dv[dir*DI+d];
    const float* dlp = g_dl + ((size_t)dir*DI+d)*NPIX;
    const float* up  = g_u  + ((size_t)dir*DI+d)*NPIX;
    const float* Bp  = g_Bmb + (size_t)dir*NPIX*DS;
    const float* Cp  = g_Cmb + (size_t)dir*NPIX*DS;
    const float* zp  = g_xzT + (((size_t)dir*2+1)*DI+d)*NPIX;
    float* gp = (dir ? g_gb1 : g_gb0) + (size_t)d*NPIX;
    float h = g_Hsb[(((size_t)dir*DI+d)*DS+n)*NCHUNK + chunk];
    int s0 = chunk*CLEN;
    for (int t=0;t<CLEN;t++){
        int s = s0+t;
        int tok = dir ? (NPIX-1-s) : s;
        float dd = dlp[tok];
        float uu = up[tok];
        float a = __expf(dd*Aa);
        h = h*a + dd*uu*Bp[(size_t)tok*DS+n];
        float cc = h*Cp[(size_t)tok*DS+n];
        cc += __shfl_xor_sync(0xffffffffu, cc, 8);
        cc += __shfl_xor_sync(0xffffffffu, cc, 4);
        cc += __shfl_xor_sync(0xffffffffu, cc, 2);
        cc += __shfl_xor_sync(0xffffffffu, cc, 1);
        if (n==0){
            float z = zp[tok];
            gp[tok] = (cc + uu*Dd) * (z/(1.f+__expf(-z)));
        }
    }
}

// ---------------- residual helpers ----------------
__global__ void k_addpix(const float* __restrict__ base, float* __restrict__ outb)
{
    int p = blockIdx.x*blockDim.x + threadIdx.x;
    if (p >= NPIX) return;
    int c = blockIdx.y;
    int h = p/HWD, w = p%HWD;
    int nh=h/5, pi=h%5, nw=w/5, pj=w%5;
    int tok = (pi*5+pj)*LPIX + nh*24+nw;
    outb[(size_t)c*NPIX+p] = base[(size_t)c*NPIX+p] + g_yo[(size_t)c*NPIX+tok];
}

__global__ void k_add3(float* __restrict__ cur, const float* __restrict__ buf)
{
    int p = blockIdx.x*blockDim.x + threadIdx.x;
    if (p >= NPIX) return;
    int c = blockIdx.y;
    size_t i = (size_t)c*NPIX+p;
    cur[i] = cur[i] + buf[i] + g_yo[i];
}

__global__ void k_transpose(const float* __restrict__ src, float* __restrict__ dst)
{
    int p = blockIdx.x*blockDim.x + threadIdx.x;
    if (p >= NPIX) return;
    int c = blockIdx.y;
    int h = p/HWD, w = p%HWD;
    dst[(size_t)c*NPIX+p] = src[(size_t)c*NPIX + w*HWD + h];
}

// ---------------- GCN hub handling ----------------
__global__ void k_hubmean(const float* __restrict__ X)
{
    int f = blockIdx.x;
    __shared__ float sm[256];
    float s = 0.f;
    for (int k=threadIdx.x;k<450;k+=256) s += X[(size_t)f*NPIX + k*32];
    sm[threadIdx.x]=s; __syncthreads();
    for (int st=128;st>0;st>>=1){
        if (threadIdx.x<st) sm[threadIdx.x]+=sm[threadIdx.x+st];
        __syncthreads();
    }
    if (threadIdx.x==0) g_hub[f]=sm[0]*(1.f/450.f);
}

__global__ void k_hubapply(float* __restrict__ X, const float* __restrict__ bias, int doRelu)
{
    int m = blockIdx.x*blockDim.x + threadIdx.x;
    if (m >= NPIX) return;
    int f = blockIdx.y;
    float v = X[(size_t)f*NPIX+m];
    if ((m & 31) == 0) v = g_hub[f];
    v += bias[f];
    if (doRelu) v = fmaxf(v, 0.f);
    X[(size_t)f*NPIX+m] = v;
}

__global__ void k_final(const float* __restrict__ x, float* __restrict__ out)
{
    int p = blockIdx.x*blockDim.x + threadIdx.x;
    if (p >= NPIX) return;
    int c = blockIdx.y;
    int h = p/HWD, w = p%HWD;
    out[(size_t)c*NPIX+p] = x[(size_t)c*NPIX+p] + g_curA[(size_t)c*NPIX+p]
        + g_curB[(size_t)c*NPIX + w*HWD + h] + g_t2[(size_t)c*NPIX+p];
}

// ---------------- host driver ----------------
static void mamba_inv(const float* img, int pixelMode, int i,
    const float* in_w_all, const float* conv_w_all, const float* conv_b_all,
    const float* xproj_all, const float* dt_w_all, const float* dt_b_all,
    const float* Alog_all, const float* D_all,
    const float* lng, const float* lnb,
    float* p_xn, float* p_xzT, float* p_u, float* p_dbl)
{
    const float* in_w   = in_w_all   + (size_t)i*2*2*DI*CM;
    const float* conv_w = conv_w_all + (size_t)i*2*DI*4;
    const float* conv_b = conv_b_all + (size_t)i*2*DI;
    const float* xproj  = xproj_all  + (size_t)i*2*36*DI;
    const float* dt_w   = dt_w_all   + (size_t)i*2*DI*4;
    const float* dt_b   = dt_b_all   + (size_t)i*2*DI;
    const float* Alog   = Alog_all   + (size_t)i*2*DI*DS;
    const float* Dv     = D_all      + (size_t)i*2*DI;
    const float* lg     = lng + (size_t)i*CM;
    const float* lb     = lnb + (size_t)i*CM;

    k_ln<<<113,128>>>(img, lg, lb, pixelMode);
    // in-proj: N=512 rows total, BN=128 -> grid y=4
    k_gemm2<8><<<dim3(225,4),256>>>(p_xn, nullptr, in_w, p_xzT,
                                    NPIX, CM, 128, 128, 128, 0, 0);
    k_convu<<<dim3(57,DI,2),256>>>(conv_w, conv_b, pixelMode?LPIX:NPIX);
    // xproj: per-dir 36 valid rows padded to 64, X row base per dir = 128
    k_gemm2<4><<<dim3(225,2),256>>>(p_u, nullptr, xproj, p_dbl,
                                    NPIX, DI, 36, 36, 64, DI, 0);
    k_dtbc<<<dim3(57,2),256>>>(dt_w, dt_b);
    if (pixelMode){
        k_scan_pix<<<dim3(8,25,2),256>>>(Alog, Dv);
    } else {
        k_scan_win1<<<dim3(8,NCHUNK,2),256>>>(Alog);
        k_scan_win2<<<4,1024>>>();
        k_scan_win3<<<dim3(8,NCHUNK,2),256>>>(Alog, Dv);
    }
}

extern "C" void kernel_launch(void* const* d_in, const int* in_sizes, int n_in,
                              void* d_out, int out_size)
{
    const float* A[28];
    if (in_sizes[9] == 256){
        const int map[28] = {0,1,2,3,4,5,6,7,8, 11,12,13,14,15,16,17,18,
                             9,10, 19,20, 21,22,23,24,25,26,27};
        for (int k=0;k<28;k++) A[k]=(const float*)d_in[map[k]];
    } else {
        for (int k=0;k<28;k++) A[k]=(const float*)d_in[k];
    }
    const float* x = A[0];
    float *p_xn,*p_xzT,*p_u,*p_dbl,*p_gb0,*p_gb1,*p_yo,*p_curA,*p_curB,*p_bufA,*p_nf,*p_t1,*p_t2;
    cudaGetSymbolAddress((void**)&p_xn,  g_xn);
    cudaGetSymbolAddress((void**)&p_xzT, g_xzT);
    cudaGetSymbolAddress((void**)&p_u,   g_u);
    cudaGetSymbolAddress((void**)&p_dbl, g_dbl);
    cudaGetSymbolAddress((void**)&p_gb0, g_gb0);
    cudaGetSymbolAddress((void**)&p_gb1, g_gb1);
    cudaGetSymbolAddress((void**)&p_yo,  g_yo);
    cudaGetSymbolAddress((void**)&p_curA,g_curA);
    cudaGetSymbolAddress((void**)&p_curB,g_curB);
    cudaGetSymbolAddress((void**)&p_bufA,g_bufA);
    cudaGetSymbolAddress((void**)&p_nf,  g_nf);
    cudaGetSymbolAddress((void**)&p_t1,  g_t1);
    cudaGetSymbolAddress((void**)&p_t2,  g_t2);

    auto run_branch = [&](float* cur, int base, float* nfx, float* nfy){
        for (int s=0;s<2;s++){
            int i = base+s;
            // pixel mamba
            mamba_inv(cur, 1, i, A[1],A[2],A[3],A[4],A[5],A[6],A[7],A[8],
                      A[17],A[18], p_xn, p_xzT, p_u, p_dbl);
            k_gemm2<4><<<dim3(225,1),256>>>(p_gb0, p_gb1, A[21] + (size_t)i*CM*DI, p_yo,
                                            NPIX, DI, 64, 64, 64, 0, 0);
            k_addpix<<<dim3(113,CM),128>>>(cur, p_bufA);
            // window mamba
            mamba_inv(p_bufA, 0, i, A[9],A[10],A[11],A[12],A[13],A[14],A[15],A[16],
                      A[19],A[20], p_xn, p_xzT, p_u, p_dbl);
            k_gemm2<4><<<dim3(225,1),256>>>(p_gb0, p_gb1, A[22] + (size_t)i*CM*DI, p_yo,
                                            NPIX, DI, 64, 64, 64, 0, 0);
            if (s==1){
                k_gemm2<4><<<dim3(225,1),256>>>(p_gb0, nullptr, A[22] + (size_t)i*CM*DI, nfx,
                                                NPIX, DI, 64, 64, 64, 0, 0);
                k_gemm2<4><<<dim3(225,1),256>>>(p_gb1, nullptr, A[23] + (size_t)i*CM*DI, nfy,
                                                NPIX, DI, 64, 64, 64, 0, 1);
            }
            k_add3<<<dim3(113,CM),128>>>(cur, p_bufA);
        }
    };

    // branch 0 (original orientation)
    cudaMemcpyAsync(p_curA, x, sizeof(float)*CM*NPIX, cudaMemcpyDeviceToDevice);
    run_branch(p_curA, 0, p_nf + 0*(size_t)CM*NPIX, p_nf + 1*(size_t)CM*NPIX);

    // branch 1 (transposed orientation)
    k_transpose<<<dim3(113,CM),128>>>(x, p_curB);
    run_branch(p_curB, 2, p_nf + 2*(size_t)CM*NPIX, p_nf + 3*(size_t)CM*NPIX);

    // GCN: layer 1 (256 -> 128)
    k_gemm2<8><<<dim3(225,1),256>>>(p_nf, nullptr, A[24], p_t1,
                                    NPIX, 4*CM, 128, 128, 128, 0, 0);
    k_hubmean<<<2*CM,256>>>(p_t1);
    k_hubapply<<<dim3(113,2*CM),128>>>(p_t1, A[25], 1);
    // layer 2 (128 -> 64)
    k_gemm2<4><<<dim3(225,1),256>>>(p_t1, nullptr, A[26], p_t2,
                                    NPIX, 2*CM, 64, 64, 64, 0, 0);
    k_hubmean<<<CM,256>>>(p_t2);
    k_hubapply<<<dim3(113,CM),128>>>(p_t2, A[27], 0);

    // final: gcn + old + lastx + lastx_T^T
    k_final<<<dim3(113,CM),128>>>(x, (float*)d_out);
}

// round 5
// speedup vs baseline: 1.4308x; 1.3092x over previous
#include <cuda_runtime.h>
#include <math.h>

#define CM 64      // d_model
#define DI 128     // d_inner
#define DS 16      // d_state
#define NPIX 14400
#define HWD 120
#define LPIX 576
#define NCHUNK 100
#define CLEN 144

// ---------------- static scratch, slotted per branch ----------------
__device__ float g_xn [2][CM*NPIX];
__device__ float g_xzT[2][2*2*DI*NPIX];   // [dir][256][tok]; rows 0..127 xh, 128..255 z
__device__ float g_u  [2][2*DI*NPIX];
__device__ float g_dl [2][2*DI*NPIX];
__device__ float g_dbl[2][2*64*NPIX];     // xproj output, rows 0..35 valid (pad 64)
__device__ float g_Bmb[2][2*NPIX*DS];
__device__ float g_Cmb[2][2*NPIX*DS];
__device__ float g_gb0[2][DI*NPIX];
__device__ float g_gb1[2][DI*NPIX];
__device__ float g_cur[2][CM*NPIX];
__device__ float g_buf[2][CM*NPIX];
__device__ float g_P  [2][2*DI*DS*NCHUNK];
__device__ float g_He [2][2*DI*DS*NCHUNK];
__device__ float g_Hsb[2][2*DI*DS*NCHUNK];
__device__ float g_nf [4*CM*NPIX];
__device__ float g_t1 [2*CM*NPIX];
__device__ float g_t2 [CM*NPIX];
__device__ float g_hub[2*CM];

// ---------------- LayerNorm + gather ----------------
__global__ void k_ln(const float* __restrict__ img, const float* __restrict__ g,
                     const float* __restrict__ b, int pixelMode, int sl)
{
    int tok = blockIdx.x*blockDim.x + threadIdx.x;
    if (tok >= NPIX) return;
    int p;
    if (pixelMode){
        int sq = tok/LPIX, l = tok%LPIX;
        int nh = l/24, nw = l%24, pi = sq/5, pj = sq%5;
        p = (nh*5+pi)*HWD + (nw*5+pj);
    } else p = tok;
    float xl[CM];
    float s = 0.f;
#pragma unroll
    for (int c=0;c<CM;c++){ xl[c] = img[(size_t)c*NPIX+p]; s += xl[c]; }
    float m = s*(1.f/CM), v = 0.f;
#pragma unroll
    for (int c=0;c<CM;c++){ float d = xl[c]-m; v += d*d; }
    float rs = rsqrtf(v*(1.f/CM) + 1e-5f);
#pragma unroll
    for (int c=0;c<CM;c++) g_xn[sl][(size_t)c*NPIX+tok] = (xl[c]-m)*rs*g[c] + b[c];
}

// --------- GEMM2: acc[n][m] = sum_k W[wbase+n][k]*(X+X2)[xbase+k][m] ----------
// mode 0: C[n][m or M-1-m] = acc
// mode 1: C[n][pixmap(m)] = base[n][pixmap(m)] + acc   (pixel residual scatter)
// mode 2: C[n][m] = C[n][m] + base[n][m] + acc         (window residual)
template<int TN>
__global__ __launch_bounds__(256) void k_gemm2(const float* __restrict__ X,
        const float* __restrict__ X2, const float* __restrict__ W,
        float* __restrict__ C, const float* __restrict__ base,
        int M, int K, int NW, int WS, int CS, int XS, int rev, int mode)
{
    constexpr int BN = 16*TN;
    __shared__ __align__(16) float Xs[32][64];
    __shared__ float Ws[BN][33];
    int t0 = blockIdx.x*64;
    int wbase = blockIdx.y*WS;
    int cbase = blockIdx.y*CS;
    int xbase = blockIdx.y*XS;
    int tid = threadIdx.x;
    int tg = tid & 15, eg = tid >> 4;
    float acc[TN][4];
#pragma unroll
    for (int j=0;j<TN;j++){ acc[j][0]=0.f; acc[j][1]=0.f; acc[j][2]=0.f; acc[j][3]=0.f; }
    for (int k0=0;k0<K;k0+=32){
#pragma unroll
        for (int r=0;r<2;r++){
            int i = tid + r*256;
            int kk = i>>4, tt = (i&15)*4;
            size_t gidx = (size_t)(xbase+k0+kk)*M + t0+tt;
            float4 v = *(const float4*)&X[gidx];
            if (X2){
                float4 w = *(const float4*)&X2[gidx];
                v.x+=w.x; v.y+=w.y; v.z+=w.z; v.w+=w.w;
            }
            *(float4*)&Xs[kk][tt] = v;
        }
#pragma unroll
        for (int r=0;r<BN/32;r++){
            int i = tid + r*256;
            int e = i>>3, kkb = (i&7)*4;
            float4 v = make_float4(0.f,0.f,0.f,0.f);
            if (e < NW) v = *(const float4*)&W[(size_t)(wbase+e)*K + k0+kkb];
            Ws[e][kkb+0]=v.x; Ws[e][kkb+1]=v.y; Ws[e][kkb+2]=v.z; Ws[e][kkb+3]=v.w;
        }
        __syncthreads();
#pragma unroll 8
        for (int kk=0;kk<32;kk++){
            float4 xv = *(const float4*)&Xs[kk][tg*4];
#pragma unroll
            for (int j=0;j<TN;j++){
                float wv = Ws[eg*TN+j][kk];
                acc[j][0] += xv.x*wv; acc[j][1] += xv.y*wv;
                acc[j][2] += xv.z*wv; acc[j][3] += xv.w*wv;
            }
        }
        __syncthreads();
    }
#pragma unroll
    for (int j=0;j<TN;j++){
        size_t row = (size_t)(cbase + eg*TN + j)*M;
        if (mode == 0){
            if (!rev){
                float4 o = make_float4(acc[j][0],acc[j][1],acc[j][2],acc[j][3]);
                *(float4*)&C[row + t0 + tg*4] = o;
            } else {
#pragma unroll
                for (int mj=0;mj<4;mj++) C[row + (M-1-(t0+tg*4+mj))] = acc[j][mj];
            }
        } else if (mode == 1){
#pragma unroll
            for (int mj=0;mj<4;mj++){
                int tok = t0 + tg*4 + mj;
                int sq = tok/LPIX, l = tok%LPIX;
                int nh = l/24, nw = l%24, pi = sq/5, pj = sq%5;
                int p = (nh*5+pi)*HWD + (nw*5+pj);
                C[row + p] = base[row + p] + acc[j][mj];
            }
        } else {
            size_t i = row + t0 + tg*4;
            float4 b = *(const float4*)&base[i];
            float4 c = *(const float4*)&C[i];
            c.x += b.x + acc[j][0]; c.y += b.y + acc[j][1];
            c.z += b.z + acc[j][2]; c.w += b.w + acc[j][3];
            *(float4*)&C[i] = c;
        }
    }
}

// ---------------- conv + silu -> u ----------------
__global__ void k_convu(const float* __restrict__ conv_w, const float* __restrict__ conv_b,
                        int Lseq, int sl)
{
    int tok = blockIdx.x*blockDim.x + threadIdx.x;
    if (tok >= NPIX) return;
    int ch = blockIdx.y, dir = blockIdx.z;
    int l = tok % Lseq;
    const float* row = g_xzT[sl] + ((size_t)dir*2*DI + ch)*NPIX;
    const float* cw = conv_w + ((size_t)dir*DI + ch)*4;
    float acc = conv_b[dir*DI + ch];
    if (dir==0){
#pragma unroll
        for (int j=0;j<4;j++) if (l>=j) acc += row[tok-j]*cw[3-j];
    } else {
#pragma unroll
        for (int j=0;j<4;j++) if (l+j<Lseq) acc += row[tok+j]*cw[3-j];
    }
    g_u[sl][((size_t)dir*DI+ch)*NPIX + tok] = acc/(1.f+__expf(-acc));
}

// --------- dt-proj + softplus + B/C pack ----------
__global__ __launch_bounds__(256) void k_dtbc(const float* __restrict__ dt_w,
    const float* __restrict__ dt_b, int sl)
{
    int dir = blockIdx.y;
    __shared__ float dw[4][DI];
    __shared__ float db[DI];
    for (int t=threadIdx.x; t<DI*4; t+=blockDim.x)
        dw[t&3][t>>2] = dt_w[(size_t)dir*DI*4 + t];
    for (int t=threadIdx.x; t<DI; t+=blockDim.x) db[t] = dt_b[dir*DI + t];
    __syncthreads();
    int tok = blockIdx.x*blockDim.x + threadIdx.x;
    if (tok >= NPIX) return;
    const float* dbl = g_dbl[sl] + (size_t)dir*64*NPIX;
    float d0 = dbl[0*NPIX+tok], d1 = dbl[1*NPIX+tok];
    float d2 = dbl[2*NPIX+tok], d3 = dbl[3*NPIX+tok];
#pragma unroll 8
    for (int ch=0; ch<DI; ch++){
        float t = db[ch] + dw[0][ch]*d0 + dw[1][ch]*d1 + dw[2][ch]*d2 + dw[3][ch]*d3;
        t = (t>20.f)? t : log1pf(__expf(t));
        g_dl[sl][((size_t)dir*DI+ch)*NPIX + tok] = t;
    }
    size_t bo = ((size_t)dir*NPIX + tok)*DS;
#pragma unroll
    for (int q=0;q<4;q++){
        float4 vb = make_float4(dbl[(4+q*4+0)*NPIX+tok], dbl[(4+q*4+1)*NPIX+tok],
                                dbl[(4+q*4+2)*NPIX+tok], dbl[(4+q*4+3)*NPIX+tok]);
        *(float4*)&g_Bmb[sl][bo + q*4] = vb;
        float4 vc = make_float4(dbl[(20+q*4+0)*NPIX+tok], dbl[(20+q*4+1)*NPIX+tok],
                                dbl[(20+q*4+2)*NPIX+tok], dbl[(20+q*4+3)*NPIX+tok]);
        *(float4*)&g_Cmb[sl][bo + q*4] = vc;
    }
}

// ---------------- pixel scan + fused gate ----------------
__global__ void k_scan_pix(const float* __restrict__ Alog, const float* __restrict__ Dv, int sl)
{
    int dir = blockIdx.z, seq = blockIdx.y;
    int n = threadIdx.x & 15;
    int d = blockIdx.x*16 + (threadIdx.x>>4);
    float Aa = -__expf(Alog[((size_t)dir*DI+d)*DS+n]);
    float Dd = Dv[dir*DI+d];
    const float* dlp = g_dl[sl] + ((size_t)dir*DI+d)*NPIX;
    const float* up  = g_u [sl] + ((size_t)dir*DI+d)*NPIX;
    const float* Bp  = g_Bmb[sl] + (size_t)dir*NPIX*DS;
    const float* Cp  = g_Cmb[sl] + (size_t)dir*NPIX*DS;
    const float* zp  = g_xzT[sl] + (((size_t)dir*2+1)*DI+d)*NPIX;
    float* gp = (dir ? g_gb1[sl] : g_gb0[sl]) + (size_t)d*NPIX;
    float h = 0.f;
    int s0 = seq*LPIX;
    for (int t=0;t<LPIX;t++){
        int tok = s0 + (dir ? (LPIX-1-t) : t);
        float dd = dlp[tok];
        float uu = up[tok];
        float a = __expf(dd*Aa);
        h = h*a + dd*uu*Bp[(size_t)tok*DS+n];
        float cc = h*Cp[(size_t)tok*DS+n];
        cc += __shfl_xor_sync(0xffffffffu, cc, 8);
        cc += __shfl_xor_sync(0xffffffffu, cc, 4);
        cc += __shfl_xor_sync(0xffffffffu, cc, 2);
        cc += __shfl_xor_sync(0xffffffffu, cc, 1);
        if (n==0){
            float z = zp[tok];
            gp[tok] = (cc + uu*Dd) * (z/(1.f+__expf(-z)));
        }
    }
}

// ---------------- window scan: 3-phase chunked linear recurrence -------------
__global__ void k_scan_win1(const float* __restrict__ Alog, int sl)
{
    int dir = blockIdx.z, chunk = blockIdx.y;
    int n = threadIdx.x & 15;
    int d = blockIdx.x*16 + (threadIdx.x>>4);
    float Aa = -__expf(Alog[((size_t)dir*DI+d)*DS+n]);
    const float* dlp = g_dl[sl] + ((size_t)dir*DI+d)*NPIX;
    const float* up  = g_u [sl] + ((size_t)dir*DI+d)*NPIX;
    const float* Bp  = g_Bmb[sl] + (size_t)dir*NPIX*DS;
    float h = 0.f, p = 1.f;
    int s0 = chunk*CLEN;
    for (int t=0;t<CLEN;t++){
        int s = s0+t;
        int tok = dir ? (NPIX-1-s) : s;
        float dd = dlp[tok];
        float a = __expf(dd*Aa);
        h = h*a + dd*up[tok]*Bp[(size_t)tok*DS+n];
        p *= a;
    }
    size_t idx = (((size_t)dir*DI+d)*DS+n)*NCHUNK + chunk;
    g_P[sl][idx]=p; g_He[sl][idx]=h;
}

__global__ void k_scan_win2(int sl)
{
    int idx = blockIdx.x*blockDim.x + threadIdx.x;
    if (idx >= 2*DI*DS) return;
    size_t base = (size_t)idx*NCHUNK;
    float h = 0.f;
    for (int c=0;c<NCHUNK;c++){
        g_Hsb[sl][base+c] = h;
        h = g_He[sl][base+c] + g_P[sl][base+c]*h;
    }
}

__global__ void k_scan_win3(const float* __restrict__ Alog, const float* __restrict__ Dv, int sl)
{
    int dir = blockIdx.z, chunk = blockIdx.y;
    int n = threadIdx.x & 15;
    int d = blockIdx.x*16 + (threadIdx.x>>4);
    float Aa = -__expf(Alog[((size_t)dir*DI+d)*DS+n]);
    float Dd = Dv[dir*DI+d];
    const float* dlp = g_dl[sl] + ((size_t)dir*DI+d)*NPIX;
    const float* up  = g_u [sl] + ((size_t)dir*DI+d)*NPIX;
    const float* Bp  = g_Bmb[sl] + (size_t)dir*NPIX*DS;
    const float* Cp  = g_Cmb[sl] + (size_t)dir*NPIX*DS;
    const float* zp  = g_xzT[sl] + (((size_t)dir*2+1)*DI+d)*NPIX;
    float* gp = (dir ? g_gb1[sl] : g_gb0[sl]) + (size_t)d*NPIX;
    float h = g_Hsb[sl][(((size_t)dir*DI+d)*DS+n)*NCHUNK + chunk];
    int s0 = chunk*CLEN;
    for (int t=0;t<CLEN;t++){
        int s = s0+t;
        int tok = dir ? (NPIX-1-s) : s;
        float dd = dlp[tok];
        float uu = up[tok];
        float a = __expf(dd*Aa);
        h = h*a + dd*uu*Bp[(size_t)tok*DS+n];
        float cc = h*Cp[(size_t)tok*DS+n];
        cc += __shfl_xor_sync(0xffffffffu, cc, 8);
        cc += __shfl_xor_sync(0xffffffffu, cc, 4);
        cc += __shfl_xor_sync(0xffffffffu, cc, 2);
        cc += __shfl_xor_sync(0xffffffffu, cc, 1);
        if (n==0){
            float z = zp[tok];
            gp[tok] = (cc + uu*Dd) * (z/(1.f+__expf(-z)));
        }
    }
}

// ---------------- misc ----------------
__global__ void k_transpose(const float* __restrict__ src, float* __restrict__ dst)
{
    int p = blockIdx.x*blockDim.x + threadIdx.x;
    if (p >= NPIX) return;
    int c = blockIdx.y;
    int h = p/HWD, w = p%HWD;
    dst[(size_t)c*NPIX+p] = src[(size_t)c*NPIX + w*HWD + h];
}

__global__ void k_hubmean(const float* __restrict__ X)
{
    int f = blockIdx.x;
    __shared__ float sm[256];
    float s = 0.f;
    for (int k=threadIdx.x;k<450;k+=256) s += X[(size_t)f*NPIX + k*32];
    sm[threadIdx.x]=s; __syncthreads();
    for (int st=128;st>0;st>>=1){
        if (threadIdx.x<st) sm[threadIdx.x]+=sm[threadIdx.x+st];
        __syncthreads();
    }
    if (threadIdx.x==0) g_hub[f]=sm[0]*(1.f/450.f);
}

__global__ void k_hubapply(float* __restrict__ X, const float* __restrict__ bias, int doRelu)
{
    int m = blockIdx.x*blockDim.x + threadIdx.x;
    if (m >= NPIX) return;
    int f = blockIdx.y;
    float v = X[(size_t)f*NPIX+m];
    if ((m & 31) == 0) v = g_hub[f];
    v += bias[f];
    if (doRelu) v = fmaxf(v, 0.f);
    X[(size_t)f*NPIX+m] = v;
}

__global__ void k_final(const float* __restrict__ x, float* __restrict__ out)
{
    int p = blockIdx.x*blockDim.x + threadIdx.x;
    if (p >= NPIX) return;
    int c = blockIdx.y;
    int h = p/HWD, w = p%HWD;
    out[(size_t)c*NPIX+p] = x[(size_t)c*NPIX+p] + g_cur[0][(size_t)c*NPIX+p]
        + g_cur[1][(size_t)c*NPIX + w*HWD + h] + g_t2[(size_t)c*NPIX+p];
}

// ---------------- host driver ----------------
struct Ptrs {
    float *xn, *xzT, *u, *dbl, *gb0, *gb1, *cur, *buf;
};

static void mamba_inv(cudaStream_t st, const Ptrs& P, int sl,
    const float* img, int pixelMode, int i,
    const float* in_w_all, const float* conv_w_all, const float* conv_b_all,
    const float* xproj_all, const float* dt_w_all, const float* dt_b_all,
    const float* Alog_all, const float* D_all,
    const float* lng, const float* lnb)
{
    const float* in_w   = in_w_all   + (size_t)i*2*2*DI*CM;
    const float* conv_w = conv_w_all + (size_t)i*2*DI*4;
    const float* conv_b = conv_b_all + (size_t)i*2*DI;
    const float* xproj  = xproj_all  + (size_t)i*2*36*DI;
    const float* dt_w   = dt_w_all   + (size_t)i*2*DI*4;
    const float* dt_b   = dt_b_all   + (size_t)i*2*DI;
    const float* Alog   = Alog_all   + (size_t)i*2*DI*DS;
    const float* Dv     = D_all      + (size_t)i*2*DI;
    const float* lg     = lng + (size_t)i*CM;
    const float* lb     = lnb + (size_t)i*CM;

    k_ln<<<113,128,0,st>>>(img, lg, lb, pixelMode, sl);
    k_gemm2<8><<<dim3(225,4),256,0,st>>>(P.xn, nullptr, in_w, P.xzT, nullptr,
                                         NPIX, CM, 128, 128, 128, 0, 0, 0);
    k_convu<<<dim3(57,DI,2),256,0,st>>>(conv_w, conv_b, pixelMode?LPIX:NPIX, sl);
    k_gemm2<4><<<dim3(225,2),256,0,st>>>(P.u, nullptr, xproj, P.dbl, nullptr,
                                         NPIX, DI, 36, 36, 64, DI, 0, 0);
    k_dtbc<<<dim3(57,2),256,0,st>>>(dt_w, dt_b, sl);
    if (pixelMode){
        k_scan_pix<<<dim3(8,25,2),256,0,st>>>(Alog, Dv, sl);
    } else {
        k_scan_win1<<<dim3(8,NCHUNK,2),256,0,st>>>(Alog, sl);
        k_scan_win2<<<4,1024,0,st>>>(sl);
        k_scan_win3<<<dim3(8,NCHUNK,2),256,0,st>>>(Alog, Dv, sl);
    }
}

extern "C" void kernel_launch(void* const* d_in, const int* in_sizes, int n_in,
                              void* d_out, int out_size)
{
    const float* A[28];
    if (in_sizes[9] == 256){
        const int map[28] = {0,1,2,3,4,5,6,7,8, 11,12,13,14,15,16,17,18,
                             9,10, 19,20, 21,22,23,24,25,26,27};
        for (int k=0;k<28;k++) A[k]=(const float*)d_in[map[k]];
    } else {
        for (int k=0;k<28;k++) A[k]=(const float*)d_in[k];
    }
    const float* x = A[0];

    static cudaStream_t s[2] = {nullptr, nullptr};
    static cudaEvent_t evFork = nullptr, evJoin0 = nullptr, evJoin1 = nullptr;
    if (!s[0]){
        cudaStreamCreateWithFlags(&s[0], cudaStreamNonBlocking);
        cudaStreamCreateWithFlags(&s[1], cudaStreamNonBlocking);
        cudaEventCreateWithFlags(&evFork,  cudaEventDisableTiming);
        cudaEventCreateWithFlags(&evJoin0, cudaEventDisableTiming);
        cudaEventCreateWithFlags(&evJoin1, cudaEventDisableTiming);
    }

    Ptrs P[2];
    float *p_nf, *p_t1, *p_t2;
    {
        float* q;
        cudaGetSymbolAddress((void**)&q, g_xn);   P[0].xn  = q; P[1].xn  = q + (size_t)CM*NPIX;
        cudaGetSymbolAddress((void**)&q, g_xzT);  P[0].xzT = q; P[1].xzT = q + (size_t)2*2*DI*NPIX;
        cudaGetSymbolAddress((void**)&q, g_u);    P[0].u   = q; P[1].u   = q + (size_t)2*DI*NPIX;
        cudaGetSymbolAddress((void**)&q, g_dbl);  P[0].dbl = q; P[1].dbl = q + (size_t)2*64*NPIX;
        cudaGetSymbolAddress((void**)&q, g_gb0);  P[0].gb0 = q; P[1].gb0 = q + (size_t)DI*NPIX;
        cudaGetSymbolAddress((void**)&q, g_gb1);  P[0].gb1 = q; P[1].gb1 = q + (size_t)DI*NPIX;
        cudaGetSymbolAddress((void**)&q, g_cur);  P[0].cur = q; P[1].cur = q + (size_t)CM*NPIX;
        cudaGetSymbolAddress((void**)&q, g_buf);  P[0].buf = q; P[1].buf = q + (size_t)CM*NPIX;
        cudaGetSymbolAddress((void**)&p_nf, g_nf);
        cudaGetSymbolAddress((void**)&p_t1, g_t1);
        cudaGetSymbolAddress((void**)&p_t2, g_t2);
    }

    // fork both branch streams from the capture (null) stream
    cudaEventRecord(evFork, 0);
    cudaStreamWaitEvent(s[0], evFork, 0);
    cudaStreamWaitEvent(s[1], evFork, 0);

    auto run_branch = [&](int sl, int base, float* nfx, float* nfy){
        cudaStream_t st = s[sl];
        const Ptrs& Q = P[sl];
        for (int sstage=0; sstage<2; sstage++){
            int i = base+sstage;
            // pixel mamba on cur
            mamba_inv(st, Q, sl, Q.cur, 1, i, A[1],A[2],A[3],A[4],A[5],A[6],A[7],A[8],
                      A[17],A[18]);
            // buf = cur + pixel residual (scatter epilogue)
            k_gemm2<4><<<dim3(225,1),256,0,st>>>(Q.gb0, Q.gb1, A[21] + (size_t)i*CM*DI,
                                                 Q.buf, Q.cur, NPIX, DI, 64, 64, 64, 0, 0, 1);
            // window mamba on buf
            mamba_inv(st, Q, sl, Q.buf, 0, i, A[9],A[10],A[11],A[12],A[13],A[14],A[15],A[16],
                      A[19],A[20]);
            if (sstage==1){
                k_gemm2<4><<<dim3(225,1),256,0,st>>>(Q.gb0, nullptr, A[22] + (size_t)i*CM*DI,
                                                     nfx, nullptr, NPIX, DI, 64, 64, 64, 0, 0, 0);
                k_gemm2<4><<<dim3(225,1),256,0,st>>>(Q.gb1, nullptr, A[23] + (size_t)i*CM*DI,
                                                     nfy, nullptr, NPIX, DI, 64, 64, 64, 0, 1, 0);
            }
            // cur = cur + buf + window residual
            k_gemm2<4><<<dim3(225,1),256,0,st>>>(Q.gb0, Q.gb1, A[22] + (size_t)i*CM*DI,
                                                 Q.cur, Q.buf, NPIX, DI, 64, 64, 64, 0, 0, 2);
        }
    };

    // branch 0 (original orientation) on s[0]
    cudaMemcpyAsync(P[0].cur, x, sizeof(float)*CM*NPIX, cudaMemcpyDeviceToDevice, s[0]);
    run_branch(0, 0, p_nf + 0*(size_t)CM*NPIX, p_nf + 1*(size_t)CM*NPIX);

    // branch 1 (transposed orientation) on s[1]
    k_transpose<<<dim3(113,CM),128,0,s[1]>>>(x, P[1].cur);
    run_branch(1, 2, p_nf + 2*(size_t)CM*NPIX, p_nf + 3*(size_t)CM*NPIX);

    // join back onto the capture stream
    cudaEventRecord(evJoin0, s[0]);
    cudaEventRecord(evJoin1, s[1]);
    cudaStreamWaitEvent(0, evJoin0, 0);
    cudaStreamWaitEvent(0, evJoin1, 0);

    // GCN: layer 1 (256 -> 128)
    k_gemm2<8><<<dim3(225,1),256>>>(p_nf, nullptr, A[24], p_t1, nullptr,
                                    NPIX, 4*CM, 128, 128, 128, 0, 0, 0);
    k_hubmean<<<2*CM,256>>>(p_t1);
    k_hubapply<<<dim3(113,2*CM),128>>>(p_t1, A[25], 1);
    // layer 2 (128 -> 64)
    k_gemm2<4><<<dim3(225,1),256>>>(p_t1, nullptr, A[26], p_t2, nullptr,
                                    NPIX, 2*CM, 64, 64, 64, 0, 0, 0);
    k_hubmean<<<CM,256>>>(p_t2);
    k_hubapply<<<dim3(113,CM),128>>>(p_t2, A[27], 0);

    // final: gcn + old + lastx + lastx_T^T
    k_final<<<dim3(113,CM),128>>>(x, (float*)d_out);
}

// round 6
// speedup vs baseline: 1.4591x; 1.0198x over previous
#include <cuda_runtime.h>
#include <math.h>

#define CM 64      // d_model
#define DI 128     // d_inner
#define DS 16      // d_state
#define NPIX 14400
#define HWD 120
#define LPIX 576
#define NCHUNK 100
#define CLEN 144

// ---------------- static scratch, slotted per branch ----------------
__device__ float2 g_st [2][NPIX];         // per-token layernorm (mean, rstd)
__device__ float g_xzT[2][2*2*DI*NPIX];   // [dir][256][tok]; rows 0..127 xh, 128..255 z
__device__ float g_u  [2][2*DI*NPIX];
__device__ float g_dl [2][2*DI*NPIX];
__device__ float g_dbl[2][2*64*NPIX];     // xproj output, rows 0..35 valid (pad 64)
__device__ float g_Bmb[2][2*NPIX*DS];
__device__ float g_Cmb[2][2*NPIX*DS];
__device__ float g_gb0[2][DI*NPIX];
__device__ float g_gb1[2][DI*NPIX];
__device__ float g_cur[2][CM*NPIX];
__device__ float g_buf[2][CM*NPIX];
__device__ float g_P  [2][2*DI*DS*NCHUNK];
__device__ float g_He [2][2*DI*DS*NCHUNK];
__device__ float g_Hsb[2][2*DI*DS*NCHUNK];
__device__ float g_nf [4*CM*NPIX];
__device__ float g_t1 [2*CM*NPIX];
__device__ float g_t2 [CM*NPIX];
__device__ float g_hub[2*CM];

__device__ __forceinline__ int pixmap(int t){
    int sq = t/LPIX, l = t%LPIX;
    int nh = l/24, nw = l%24, pi = sq/5, pj = sq%5;
    return (nh*5+pi)*HWD + (nw*5+pj);
}

// ---------------- LayerNorm stats (coalesced read, tiny scattered write) -----
__global__ void k_lnstat(const float* __restrict__ img, int pixelMode, float2* __restrict__ stats)
{
    int p = blockIdx.x*blockDim.x + threadIdx.x;
    if (p >= NPIX) return;
    float xl[CM];
    float s = 0.f;
#pragma unroll
    for (int c=0;c<CM;c++){ xl[c] = img[(size_t)c*NPIX+p]; s += xl[c]; }
    float m = s*(1.f/CM), v = 0.f;
#pragma unroll
    for (int c=0;c<CM;c++){ float d = xl[c]-m; v += d*d; }
    float rs = rsqrtf(v*(1.f/CM) + 1e-5f);
    int t;
    if (pixelMode){
        int h = p/HWD, w = p%HWD;
        int nh=h/5, pi=h%5, nw=w/5, pj=w%5;
        t = (pi*5+pj)*LPIX + nh*24+nw;
    } else t = p;
    stats[t] = make_float2(m, rs);
}

// --------- GEMM2: acc[n][m] = sum_k W[wbase+n][k]*Xeff[xbase+k][m] ------------
// xmode 0: Xeff = X (+X2).  xmode 1: Xeff[k][t] = (X[k][p(t)]-m_t)*rs_t*g[k]+b[k]
// mode 0: C[n][m or M-1-m] = acc
// mode 1: C[n][pixmap(m)] = base[n][pixmap(m)] + acc
// mode 2: C[n][m] = C[n][m] + base[n][m] + acc
template<int TN>
__global__ __launch_bounds__(256) void k_gemm2(const float* __restrict__ X,
        const float* __restrict__ X2, const float* __restrict__ W,
        float* __restrict__ C, const float* __restrict__ base,
        const float2* __restrict__ stats, const float* __restrict__ lng,
        const float* __restrict__ lnb,
        int M, int K, int NW, int WS, int CS, int XS,
        int rev, int mode, int xmode, int pixflag)
{
    constexpr int BN = 16*TN;
    __shared__ __align__(16) float Xs[32][64];
    __shared__ float Ws[BN][33];
    int t0 = blockIdx.x*64;
    int wbase = blockIdx.y*WS;
    int cbase = blockIdx.y*CS;
    int xbase = blockIdx.y*XS;
    int tid = threadIdx.x;
    int tg = tid & 15, eg = tid >> 4;
    float acc[TN][4];
#pragma unroll
    for (int j=0;j<TN;j++){ acc[j][0]=0.f; acc[j][1]=0.f; acc[j][2]=0.f; acc[j][3]=0.f; }
    for (int k0=0;k0<K;k0+=32){
        if (xmode == 0){
#pragma unroll
            for (int r=0;r<2;r++){
                int i = tid + r*256;
                int kk = i>>4, tt = (i&15)*4;
                size_t gidx = (size_t)(xbase+k0+kk)*M + t0+tt;
                float4 v = *(const float4*)&X[gidx];
                if (X2){
                    float4 w = *(const float4*)&X2[gidx];
                    v.x+=w.x; v.y+=w.y; v.z+=w.z; v.w+=w.w;
                }
                *(float4*)&Xs[kk][tt] = v;
            }
        } else {
#pragma unroll
            for (int r=0;r<8;r++){
                int i = tid + r*256;
                int kk = i>>6, tt = i&63;
                int ch = k0+kk;
                int t = t0+tt;
                int p = pixflag ? pixmap(t) : t;
                float2 st = stats[t];
                float raw = X[(size_t)ch*M + p];
                Xs[kk][tt] = (raw - st.x)*st.y*lng[ch] + lnb[ch];
            }
        }
#pragma unroll
        for (int r=0;r<BN/32;r++){
            int i = tid + r*256;
            int e = i>>3, kkb = (i&7)*4;
            float4 v = make_float4(0.f,0.f,0.f,0.f);
            if (e < NW) v = *(const float4*)&W[(size_t)(wbase+e)*K + k0+kkb];
            Ws[e][kkb+0]=v.x; Ws[e][kkb+1]=v.y; Ws[e][kkb+2]=v.z; Ws[e][kkb+3]=v.w;
        }
        __syncthreads();
#pragma unroll 8
        for (int kk=0;kk<32;kk++){
            float4 xv = *(const float4*)&Xs[kk][tg*4];
#pragma unroll
            for (int j=0;j<TN;j++){
                float wv = Ws[eg*TN+j][kk];
                acc[j][0] += xv.x*wv; acc[j][1] += xv.y*wv;
                acc[j][2] += xv.z*wv; acc[j][3] += xv.w*wv;
            }
        }
        __syncthreads();
    }
#pragma unroll
    for (int j=0;j<TN;j++){
        size_t row = (size_t)(cbase + eg*TN + j)*M;
        if (mode == 0){
            if (!rev){
                float4 o = make_float4(acc[j][0],acc[j][1],acc[j][2],acc[j][3]);
                *(float4*)&C[row + t0 + tg*4] = o;
            } else {
#pragma unroll
                for (int mj=0;mj<4;mj++) C[row + (M-1-(t0+tg*4+mj))] = acc[j][mj];
            }
        } else if (mode == 1){
#pragma unroll
            for (int mj=0;mj<4;mj++){
                int p = pixmap(t0 + tg*4 + mj);
                C[row + p] = base[row + p] + acc[j][mj];
            }
        } else {
            size_t i = row + t0 + tg*4;
            float4 b = *(const float4*)&base[i];
            float4 c = *(const float4*)&C[i];
            c.x += b.x + acc[j][0]; c.y += b.y + acc[j][1];
            c.z += b.z + acc[j][2]; c.w += b.w + acc[j][3];
            *(float4*)&C[i] = c;
        }
    }
}

// --------- combined stage-1 window out-proj: yo (mode2) + nfx + nfy(rev) -----
__global__ __launch_bounds__(256) void k_out3(const float* __restrict__ X0,
        const float* __restrict__ X1, const float* __restrict__ Wa,
        const float* __restrict__ Wb, float* __restrict__ cur,
        const float* __restrict__ buf, float* __restrict__ nfx, float* __restrict__ nfy)
{
    __shared__ __align__(16) float Xs0[32][64];
    __shared__ __align__(16) float Xs1[32][64];
    __shared__ float Was[64][33];
    __shared__ float Wbs[64][33];
    int t0 = blockIdx.x*64;
    int tid = threadIdx.x;
    int tg = tid & 15, eg = tid >> 4;
    float a1[4][4], a2[4][4], a3[4][4];
#pragma unroll
    for (int j=0;j<4;j++)
#pragma unroll
        for (int mj=0;mj<4;mj++){ a1[j][mj]=0.f; a2[j][mj]=0.f; a3[j][mj]=0.f; }
    for (int k0=0;k0<DI;k0+=32){
#pragma unroll
        for (int r=0;r<2;r++){
            int i = tid + r*256;
            int kk = i>>4, tt = (i&15)*4;
            size_t gidx = (size_t)(k0+kk)*NPIX + t0+tt;
            *(float4*)&Xs0[kk][tt] = *(const float4*)&X0[gidx];
            *(float4*)&Xs1[kk][tt] = *(const float4*)&X1[gidx];
        }
#pragma unroll
        for (int r=0;r<2;r++){
            int i = tid + r*256;
            int e = i>>3, kkb = (i&7)*4;
            float4 va = *(const float4*)&Wa[(size_t)e*DI + k0+kkb];
            Was[e][kkb+0]=va.x; Was[e][kkb+1]=va.y; Was[e][kkb+2]=va.z; Was[e][kkb+3]=va.w;
            float4 vb = *(const float4*)&Wb[(size_t)e*DI + k0+kkb];
            Wbs[e][kkb+0]=vb.x; Wbs[e][kkb+1]=vb.y; Wbs[e][kkb+2]=vb.z; Wbs[e][kkb+3]=vb.w;
        }
        __syncthreads();
#pragma unroll 8
        for (int kk=0;kk<32;kk++){
            float4 x0 = *(const float4*)&Xs0[kk][tg*4];
            float4 x1 = *(const float4*)&Xs1[kk][tg*4];
#pragma unroll
            for (int j=0;j<4;j++){
                float wa = Was[eg*4+j][kk];
                float wb = Wbs[eg*4+j][kk];
                a1[j][0] += x0.x*wa; a1[j][1] += x0.y*wa; a1[j][2] += x0.z*wa; a1[j][3] += x0.w*wa;
                a2[j][0] += x1.x*wa; a2[j][1] += x1.y*wa; a2[j][2] += x1.z*wa; a2[j][3] += x1.w*wa;
                a3[j][0] += x1.x*wb; a3[j][1] += x1.y*wb; a3[j][2] += x1.z*wb; a3[j][3] += x1.w*wb;
            }
        }
        __syncthreads();
    }
#pragma unroll
    for (int j=0;j<4;j++){
        size_t row = (size_t)(eg*4+j)*NPIX;
        size_t i = row + t0 + tg*4;
        float4 b = *(const float4*)&buf[i];
        float4 c = *(const float4*)&cur[i];
        c.x += b.x + a1[j][0] + a2[j][0];
        c.y += b.y + a1[j][1] + a2[j][1];
        c.z += b.z + a1[j][2] + a2[j][2];
        c.w += b.w + a1[j][3] + a2[j][3];
        *(float4*)&cur[i] = c;
        float4 fx = make_float4(a1[j][0],a1[j][1],a1[j][2],a1[j][3]);
        *(float4*)&nfx[i] = fx;
#pragma unroll
        for (int mj=0;mj<4;mj++) nfy[row + (NPIX-1-(t0+tg*4+mj))] = a3[j][mj];
    }
}

// ---------------- conv + silu -> u ----------------
__global__ void k_convu(const float* __restrict__ conv_w, const float* __restrict__ conv_b,
                        int Lseq, int sl)
{
    int tok = blockIdx.x*blockDim.x + threadIdx.x;
    if (tok >= NPIX) return;
    int ch = blockIdx.y, dir = blockIdx.z;
    int l = tok % Lseq;
    const float* row = g_xzT[sl] + ((size_t)dir*2*DI + ch)*NPIX;
    const float* cw = conv_w + ((size_t)dir*DI + ch)*4;
    float acc = conv_b[dir*DI + ch];
    if (dir==0){
#pragma unroll
        for (int j=0;j<4;j++) if (l>=j) acc += row[tok-j]*cw[3-j];
    } else {
#pragma unroll
        for (int j=0;j<4;j++) if (l+j<Lseq) acc += row[tok+j]*cw[3-j];
    }
    g_u[sl][((size_t)dir*DI+ch)*NPIX + tok] = acc/(1.f+__expf(-acc));
}

// --------- dt-proj + softplus + B/C pack ----------
__global__ __launch_bounds__(256) void k_dtbc(const float* __restrict__ dt_w,
    const float* __restrict__ dt_b, int sl)
{
    int dir = blockIdx.y;
    __shared__ float dw[4][DI];
    __shared__ float db[DI];
    for (int t=threadIdx.x; t<DI*4; t+=blockDim.x)
        dw[t&3][t>>2] = dt_w[(size_t)dir*DI*4 + t];
    for (int t=threadIdx.x; t<DI; t+=blockDim.x) db[t] = dt_b[dir*DI + t];
    __syncthreads();
    int tok = blockIdx.x*blockDim.x + threadIdx.x;
    if (tok >= NPIX) return;
    const float* dbl = g_dbl[sl] + (size_t)dir*64*NPIX;
    float d0 = dbl[0*NPIX+tok], d1 = dbl[1*NPIX+tok];
    float d2 = dbl[2*NPIX+tok], d3 = dbl[3*NPIX+tok];
#pragma unroll 8
    for (int ch=0; ch<DI; ch++){
        float t = db[ch] + dw[0][ch]*d0 + dw[1][ch]*d1 + dw[2][ch]*d2 + dw[3][ch]*d3;
        t = (t>20.f)? t : log1pf(__expf(t));
        g_dl[sl][((size_t)dir*DI+ch)*NPIX + tok] = t;
    }
    size_t bo = ((size_t)dir*NPIX + tok)*DS;
#pragma unroll
    for (int q=0;q<4;q++){
        float4 vb = make_float4(dbl[(4+q*4+0)*NPIX+tok], dbl[(4+q*4+1)*NPIX+tok],
                                dbl[(4+q*4+2)*NPIX+tok], dbl[(4+q*4+3)*NPIX+tok]);
        *(float4*)&g_Bmb[sl][bo + q*4] = vb;
        float4 vc = make_float4(dbl[(20+q*4+0)*NPIX+tok], dbl[(20+q*4+1)*NPIX+tok],
                                dbl[(20+q*4+2)*NPIX+tok], dbl[(20+q*4+3)*NPIX+tok]);
        *(float4*)&g_Cmb[sl][bo + q*4] = vc;
    }
}

// ---------------- pixel scan + fused gate ----------------
__global__ void k_scan_pix(const float* __restrict__ Alog, const float* __restrict__ Dv, int sl)
{
    int dir = blockIdx.z, seq = blockIdx.y;
    int n = threadIdx.x & 15;
    int d = blockIdx.x*16 + (threadIdx.x>>4);
    float Aa = -__expf(Alog[((size_t)dir*DI+d)*DS+n]);
    float Dd = Dv[dir*DI+d];
    const float* dlp = g_dl[sl] + ((size_t)dir*DI+d)*NPIX;
    const float* up  = g_u [sl] + ((size_t)dir*DI+d)*NPIX;
    const float* Bp  = g_Bmb[sl] + (size_t)dir*NPIX*DS;
    const float* Cp  = g_Cmb[sl] + (size_t)dir*NPIX*DS;
    const float* zp  = g_xzT[sl] + (((size_t)dir*2+1)*DI+d)*NPIX;
    float* gp = (dir ? g_gb1[sl] : g_gb0[sl]) + (size_t)d*NPIX;
    float h = 0.f;
    int s0 = seq*LPIX;
    for (int t=0;t<LPIX;t++){
        int tok = s0 + (dir ? (LPIX-1-t) : t);
        float dd = dlp[tok];
        float uu = up[tok];
        float a = __expf(dd*Aa);
        h = h*a + dd*uu*Bp[(size_t)tok*DS+n];
        float cc = h*Cp[(size_t)tok*DS+n];
        cc += __shfl_xor_sync(0xffffffffu, cc, 8);
        cc += __shfl_xor_sync(0xffffffffu, cc, 4);
        cc += __shfl_xor_sync(0xffffffffu, cc, 2);
        cc += __shfl_xor_sync(0xffffffffu, cc, 1);
        if (n==0){
            float z = zp[tok];
            gp[tok] = (cc + uu*Dd) * (z/(1.f+__expf(-z)));
        }
    }
}

// ---------------- window scan: 3-phase chunked linear recurrence -------------
__global__ void k_scan_win1(const float* __restrict__ Alog, int sl)
{
    int dir = blockIdx.z, chunk = blockIdx.y;
    int n = threadIdx.x & 15;
    int d = blockIdx.x*16 + (threadIdx.x>>4);
    float Aa = -__expf(Alog[((size_t)dir*DI+d)*DS+n]);
    const float* dlp = g_dl[sl] + ((size_t)dir*DI+d)*NPIX;
    const float* up  = g_u [sl] + ((size_t)dir*DI+d)*NPIX;
    const float* Bp  = g_Bmb[sl] + (size_t)dir*NPIX*DS;
    float h = 0.f, p = 1.f;
    int s0 = chunk*CLEN;
    for (int t=0;t<CLEN;t++){
        int s = s0+t;
        int tok = dir ? (NPIX-1-s) : s;
        float dd = dlp[tok];
        float a = __expf(dd*Aa);
        h = h*a + dd*up[tok]*Bp[(size_t)tok*DS+n];
        p *= a;
    }
    size_t idx = (((size_t)dir*DI+d)*DS+n)*NCHUNK + chunk;
    g_P[sl][idx]=p; g_He[sl][idx]=h;
}

__global__ void k_scan_win2(int sl)
{
    int idx = blockIdx.x*blockDim.x + threadIdx.x;
    if (idx >= 2*DI*DS) return;
    size_t base = (size_t)idx*NCHUNK;
    float h = 0.f;
    for (int c=0;c<NCHUNK;c++){
        g_Hsb[sl][base+c] = h;
        h = g_He[sl][base+c] + g_P[sl][base+c]*h;
    }
}

__global__ void k_scan_win3(const float* __restrict__ Alog, const float* __restrict__ Dv, int sl)
{
    int dir = blockIdx.z, chunk = blockIdx.y;
    int n = threadIdx.x & 15;
    int d = blockIdx.x*16 + (threadIdx.x>>4);
    float Aa = -__expf(Alog[((size_t)dir*DI+d)*DS+n]);
    float Dd = Dv[dir*DI+d];
    const float* dlp = g_dl[sl] + ((size_t)dir*DI+d)*NPIX;
    const float* up  = g_u [sl] + ((size_t)dir*DI+d)*NPIX;
    const float* Bp  = g_Bmb[sl] + (size_t)dir*NPIX*DS;
    const float* Cp  = g_Cmb[sl] + (size_t)dir*NPIX*DS;
    const float* zp  = g_xzT[sl] + (((size_t)dir*2+1)*DI+d)*NPIX;
    float* gp = (dir ? g_gb1[sl] : g_gb0[sl]) + (size_t)d*NPIX;
    float h = g_Hsb[sl][(((size_t)dir*DI+d)*DS+n)*NCHUNK + chunk];
    int s0 = chunk*CLEN;
    for (int t=0;t<CLEN;t++){
        int s = s0+t;
        int tok = dir ? (NPIX-1-s) : s;
        float dd = dlp[tok];
        float uu = up[tok];
        float a = __expf(dd*Aa);
        h = h*a + dd*uu*Bp[(size_t)tok*DS+n];
        float cc = h*Cp[(size_t)tok*DS+n];
        cc += __shfl_xor_sync(0xffffffffu, cc, 8);
        cc += __shfl_xor_sync(0xffffffffu, cc, 4);
        cc += __shfl_xor_sync(0xffffffffu, cc, 2);
        cc += __shfl_xor_sync(0xffffffffu, cc, 1);
        if (n==0){
            float z = zp[tok];
            gp[tok] = (cc + uu*Dd) * (z/(1.f+__expf(-z)));
        }
    }
}

// ---------------- misc ----------------
__global__ void k_transpose(const float* __restrict__ src, float* __restrict__ dst)
{
    int p = blockIdx.x*blockDim.x + threadIdx.x;
    if (p >= NPIX) return;
    int c = blockIdx.y;
    int h = p/HWD, w = p%HWD;
    dst[(size_t)c*NPIX+p] = src[(size_t)c*NPIX + w*HWD + h];
}

__global__ void k_hubmean(const float* __restrict__ X)
{
    int f = blockIdx.x;
    __shared__ float sm[256];
    float s = 0.f;
    for (int k=threadIdx.x;k<450;k+=256) s += X[(size_t)f*NPIX + k*32];
    sm[threadIdx.x]=s; __syncthreads();
    for (int st=128;st>0;st>>=1){
        if (threadIdx.x<st) sm[threadIdx.x]+=sm[threadIdx.x+st];
        __syncthreads();
    }
    if (threadIdx.x==0) g_hub[f]=sm[0]*(1.f/450.f);
}

__global__ void k_hubapply(float* __restrict__ X, const float* __restrict__ bias, int doRelu)
{
    int m = blockIdx.x*blockDim.x + threadIdx.x;
    if (m >= NPIX) return;
    int f = blockIdx.y;
    float v = X[(size_t)f*NPIX+m];
    if ((m & 31) == 0) v = g_hub[f];
    v += bias[f];
    if (doRelu) v = fmaxf(v, 0.f);
    X[(size_t)f*NPIX+m] = v;
}

__global__ void k_final(const float* __restrict__ x, float* __restrict__ out)
{
    int p = blockIdx.x*blockDim.x + threadIdx.x;
    if (p >= NPIX) return;
    int c = blockIdx.y;
    int h = p/HWD, w = p%HWD;
    out[(size_t)c*NPIX+p] = x[(size_t)c*NPIX+p] + g_cur[0][(size_t)c*NPIX+p]
        + g_cur[1][(size_t)c*NPIX + w*HWD + h] + g_t2[(size_t)c*NPIX+p];
}

// ---------------- host driver ----------------
struct Ptrs {
    float *xzT, *u, *dbl, *gb0, *gb1, *cur, *buf;
    float2 *st;
};

static void mamba_inv(cudaStream_t st, const Ptrs& P, int sl,
    const float* img, int pixelMode, int i,
    const float* in_w_all, const float* conv_w_all, const float* conv_b_all,
    const float* xproj_all, const float* dt_w_all, const float* dt_b_all,
    const float* Alog_all, const float* D_all,
    const float* lng, const float* lnb)
{
    const float* in_w   = in_w_all   + (size_t)i*2*2*DI*CM;
    const float* conv_w = conv_w_all + (size_t)i*2*DI*4;
    const float* conv_b = conv_b_all + (size_t)i*2*DI;
    const float* xproj  = xproj_all  + (size_t)i*2*36*DI;
    const float* dt_w   = dt_w_all   + (size_t)i*2*DI*4;
    const float* dt_b   = dt_b_all   + (size_t)i*2*DI;
    const float* Alog   = Alog_all   + (size_t)i*2*DI*DS;
    const float* Dv     = D_all      + (size_t)i*2*DI;
    const float* lg     = lng + (size_t)i*CM;
    const float* lb     = lnb + (size_t)i*CM;

    k_lnstat<<<113,128,0,st>>>(img, pixelMode, P.st);
    // in-proj with fused LN + gather: N=512 rows total, BN=128 -> grid y=4
    k_gemm2<8><<<dim3(225,4),256,0,st>>>(img, nullptr, in_w, P.xzT, nullptr,
                                         P.st, lg, lb,
                                         NPIX, CM, 128, 128, 128, 0, 0, 0, 1, pixelMode);
    k_convu<<<dim3(57,DI,2),256,0,st>>>(conv_w, conv_b, pixelMode?LPIX:NPIX, sl);
    k_gemm2<4><<<dim3(225,2),256,0,st>>>(P.u, nullptr, xproj, P.dbl, nullptr,
                                         nullptr, nullptr, nullptr,
                                         NPIX, DI, 36, 36, 64, DI, 0, 0, 0, 0);
    k_dtbc<<<dim3(57,2),256,0,st>>>(dt_w, dt_b, sl);
    if (pixelMode){
        k_scan_pix<<<dim3(8,25,2),256,0,st>>>(Alog, Dv, sl);
    } else {
        k_scan_win1<<<dim3(8,NCHUNK,2),256,0,st>>>(Alog, sl);
        k_scan_win2<<<4,1024,0,st>>>(sl);
        k_scan_win3<<<dim3(8,NCHUNK,2),256,0,st>>>(Alog, Dv, sl);
    }
}

extern "C" void kernel_launch(void* const* d_in, const int* in_sizes, int n_in,
                              void* d_out, int out_size)
{
    const float* A[28];
    if (in_sizes[9] == 256){
        const int map[28] = {0,1,2,3,4,5,6,7,8, 11,12,13,14,15,16,17,18,
                             9,10, 19,20, 21,22,23,24,25,26,27};
        for (int k=0;k<28;k++) A[k]=(const float*)d_in[map[k]];
    } else {
        for (int k=0;k<28;k++) A[k]=(const float*)d_in[k];
    }
    const float* x = A[0];

    static cudaStream_t s[2] = {nullptr, nullptr};
    static cudaEvent_t evFork = nullptr, evJoin0 = nullptr, evJoin1 = nullptr;
    if (!s[0]){
        cudaStreamCreateWithFlags(&s[0], cudaStreamNonBlocking);
        cudaStreamCreateWithFlags(&s[1], cudaStreamNonBlocking);
        cudaEventCreateWithFlags(&evFork,  cudaEventDisableTiming);
        cudaEventCreateWithFlags(&evJoin0, cudaEventDisableTiming);
        cudaEventCreateWithFlags(&evJoin1, cudaEventDisableTiming);
    }

    Ptrs P[2];
    float *p_nf, *p_t1, *p_t2;
    {
        float* q; float2* q2;
        cudaGetSymbolAddress((void**)&q2, g_st);  P[0].st  = q2; P[1].st  = q2 + (size_t)NPIX;
        cudaGetSymbolAddress((void**)&q, g_xzT);  P[0].xzT = q; P[1].xzT = q + (size_t)2*2*DI*NPIX;
        cudaGetSymbolAddress((void**)&q, g_u);    P[0].u   = q; P[1].u   = q + (size_t)2*DI*NPIX;
        cudaGetSymbolAddress((void**)&q, g_dbl);  P[0].dbl = q; P[1].dbl = q + (size_t)2*64*NPIX;
        cudaGetSymbolAddress((void**)&q, g_gb0);  P[0].gb0 = q; P[1].gb0 = q + (size_t)DI*NPIX;
        cudaGetSymbolAddress((void**)&q, g_gb1);  P[0].gb1 = q; P[1].gb1 = q + (size_t)DI*NPIX;
        cudaGetSymbolAddress((void**)&q, g_cur);  P[0].cur = q; P[1].cur = q + (size_t)CM*NPIX;
        cudaGetSymbolAddress((void**)&q, g_buf);  P[0].buf = q; P[1].buf = q + (size_t)CM*NPIX;
        cudaGetSymbolAddress((void**)&p_nf, g_nf);
        cudaGetSymbolAddress((void**)&p_t1, g_t1);
        cudaGetSymbolAddress((void**)&p_t2, g_t2);
    }

    // fork both branch streams from the capture (null) stream
    cudaEventRecord(evFork, 0);
    cudaStreamWaitEvent(s[0], evFork, 0);
    cudaStreamWaitEvent(s[1], evFork, 0);

    auto run_branch = [&](int sl, int base, float* nfx, float* nfy){
        cudaStream_t st = s[sl];
        const Ptrs& Q = P[sl];
        for (int sstage=0; sstage<2; sstage++){
            int i = base+sstage;
            // pixel mamba on cur
            mamba_inv(st, Q, sl, Q.cur, 1, i, A[1],A[2],A[3],A[4],A[5],A[6],A[7],A[8],
                      A[17],A[18]);
            // buf = cur + pixel residual (scatter epilogue)
            k_gemm2<4><<<dim3(225,1),256,0,st>>>(Q.gb0, Q.gb1, A[21] + (size_t)i*CM*DI,
                                                 Q.buf, Q.cur, nullptr, nullptr, nullptr,
                                                 NPIX, DI, 64, 64, 64, 0, 0, 1, 0, 0);
            // window mamba on buf
            mamba_inv(st, Q, sl, Q.buf, 0, i, A[9],A[10],A[11],A[12],A[13],A[14],A[15],A[16],
                      A[19],A[20]);
            if (sstage==1){
                // combined: cur += buf + W22*(gb0+gb1); nfx = W22*gb0; nfy = rev(W23*gb1)
                k_out3<<<225,256,0,st>>>(Q.gb0, Q.gb1,
                                         A[22] + (size_t)i*CM*DI, A[23] + (size_t)i*CM*DI,
                                         Q.cur, Q.buf, nfx, nfy);
            } else {
                // cur = cur + buf + window residual
                k_gemm2<4><<<dim3(225,1),256,0,st>>>(Q.gb0, Q.gb1, A[22] + (size_t)i*CM*DI,
                                                     Q.cur, Q.buf, nullptr, nullptr, nullptr,
                                                     NPIX, DI, 64, 64, 64, 0, 0, 2, 0, 0);
            }
        }
    };

    // branch 0 (original orientation) on s[0]
    cudaMemcpyAsync(P[0].cur, x, sizeof(float)*CM*NPIX, cudaMemcpyDeviceToDevice, s[0]);
    run_branch(0, 0, p_nf + 0*(size_t)CM*NPIX, p_nf + 1*(size_t)CM*NPIX);

    // branch 1 (transposed orientation) on s[1]
    k_transpose<<<dim3(113,CM),128,0,s[1]>>>(x, P[1].cur);
    run_branch(1, 2, p_nf + 2*(size_t)CM*NPIX, p_nf + 3*(size_t)CM*NPIX);

    // join back onto the capture stream
    cudaEventRecord(evJoin0, s[0]);
    cudaEventRecord(evJoin1, s[1]);
    cudaStreamWaitEvent(0, evJoin0, 0);
    cudaStreamWaitEvent(0, evJoin1, 0);

    // GCN: layer 1 (256 -> 128)
    k_gemm2<8><<<dim3(225,1),256>>>(p_nf, nullptr, A[24], p_t1, nullptr,
                                    nullptr, nullptr, nullptr,
                                    NPIX, 4*CM, 128, 128, 128, 0, 0, 0, 0, 0);
    k_hubmean<<<2*CM,256>>>(p_t1);
    k_hubapply<<<dim3(113,2*CM),128>>>(p_t1, A[25], 1);
    // layer 2 (128 -> 64)
    k_gemm2<4><<<dim3(225,1),256>>>(p_t1, nullptr, A[26], p_t2, nullptr,
                                    nullptr, nullptr, nullptr,
                                    NPIX, 2*CM, 64, 64, 64, 0, 0, 0, 0, 0);
    k_hubmean<<<CM,256>>>(p_t2);
    k_hubapply<<<dim3(113,CM),128>>>(p_t2, A[27], 0);

    // final: gcn + old + lastx + lastx_T^T
    k_final<<<dim3(113,CM),128>>>(x, (float*)d_out);
}

// round 7
// speedup vs baseline: 1.4672x; 1.0055x over previous
#include <cuda_runtime.h>
#include <math.h>

#define CM 64      // d_model
#define DI 128     // d_inner
#define DS 16      // d_state
#define NPIX 14400
#define HWD 120
#define LPIX 576
#define NCHUNK 100
#define CLEN 144

// ---------------- static scratch, slotted per branch ----------------
__device__ float g_xzT[2][2*2*DI*NPIX];   // [dir][256][tok]; rows 0..127 xh, 128..255 z
__device__ float g_u  [2][2*DI*NPIX];
__device__ float g_dl [2][2*DI*NPIX];
__device__ float g_Bmb[2][2*NPIX*DS];
__device__ float g_Cmb[2][2*NPIX*DS];
__device__ float g_gb0[2][DI*NPIX];
__device__ float g_gb1[2][DI*NPIX];
__device__ float g_cur[2][CM*NPIX];
__device__ float g_buf[2][CM*NPIX];
__device__ float g_P  [2][2*DI*DS*NCHUNK];
__device__ float g_He [2][2*DI*DS*NCHUNK];
__device__ float g_Hsb[2][2*DI*DS*NCHUNK];
__device__ float g_nf [4*CM*NPIX];
__device__ float g_t1 [2*CM*NPIX];
__device__ float g_t2 [CM*NPIX];
__device__ float g_hub1[2*CM];
__device__ float g_hub2[CM];

__device__ __forceinline__ int pixmap(int t){
    int sq = t/LPIX, l = t%LPIX;
    int nh = l/24, nw = l%24, pi = sq/5, pj = sq%5;
    return (nh*5+pi)*HWD + (nw*5+pj);
}

// ---------- fused LayerNorm + gather + in-proj GEMM (K=64 resident) ----------
// out rows: blockIdx.y*128 + eg*8 + j  of xzT (N=512 total)
__global__ __launch_bounds__(256) void k_inproj(const float* __restrict__ img,
        const float* __restrict__ W, float* __restrict__ C,
        const float* __restrict__ lng, const float* __restrict__ lnb, int pixflag)
{
    __shared__ __align__(16) float Xs[64][64];
    __shared__ float Ws[128][33];
    __shared__ float ms[64], rs[64];
    int t0 = blockIdx.x*64;
    int nb = blockIdx.y*128;
    int tid = threadIdx.x;
    int tg = tid & 15, eg = tid >> 4;

    // load raw X tile (gathered)
#pragma unroll
    for (int r=0;r<16;r++){
        int i = tid + r*256;
        int kk = i>>6, tt = i&63;
        int t = t0+tt;
        int p = pixflag ? pixmap(t) : t;
        Xs[kk][tt] = img[(size_t)kk*NPIX + p];
    }
    __syncthreads();
    // stats (two-pass, threads 0..63, row-wise conflict-free)
    if (tid < 64){
        float s = 0.f;
#pragma unroll
        for (int k=0;k<64;k++) s += Xs[k][tid];
        float m = s*(1.f/64.f), v = 0.f;
#pragma unroll
        for (int k=0;k<64;k++){ float d = Xs[k][tid]-m; v += d*d; }
        ms[tid] = m;
        rs[tid] = rsqrtf(v*(1.f/64.f) + 1e-5f);
    }
    __syncthreads();
    // normalize in place
#pragma unroll
    for (int r=0;r<16;r++){
        int i = tid + r*256;
        int kk = i>>6, tt = i&63;
        Xs[kk][tt] = (Xs[kk][tt]-ms[tt])*rs[tt]*lng[kk] + lnb[kk];
    }

    float acc[8][4];
#pragma unroll
    for (int j=0;j<8;j++){ acc[j][0]=0.f; acc[j][1]=0.f; acc[j][2]=0.f; acc[j][3]=0.f; }
    for (int k0=0;k0<64;k0+=32){
        __syncthreads();
#pragma unroll
        for (int r=0;r<4;r++){
            int i = tid + r*256;
            int e = i>>3, kkb = (i&7)*4;
            float4 v = *(const float4*)&W[(size_t)(nb+e)*CM + k0+kkb];
            Ws[e][kkb+0]=v.x; Ws[e][kkb+1]=v.y; Ws[e][kkb+2]=v.z; Ws[e][kkb+3]=v.w;
        }
        __syncthreads();
#pragma unroll 8
        for (int kk=0;kk<32;kk++){
            float4 xv = *(const float4*)&Xs[k0+kk][tg*4];
#pragma unroll
            for (int j=0;j<8;j++){
                float wv = Ws[eg*8+j][kk];
                acc[j][0] += xv.x*wv; acc[j][1] += xv.y*wv;
                acc[j][2] += xv.z*wv; acc[j][3] += xv.w*wv;
            }
        }
    }
#pragma unroll
    for (int j=0;j<8;j++){
        size_t row = (size_t)(nb + eg*8 + j)*NPIX;
        float4 o = make_float4(acc[j][0],acc[j][1],acc[j][2],acc[j][3]);
        *(float4*)&C[row + t0 + tg*4] = o;
    }
}

// ---- fused conv+silu (loader) + xproj GEMM + dt-proj/softplus + B/C pack ----
__global__ __launch_bounds__(256) void k_cxp(
    const float* __restrict__ conv_w, const float* __restrict__ conv_b,
    const float* __restrict__ xproj_w, const float* __restrict__ dt_w,
    const float* __restrict__ dt_b, int Lseq, int sl)
{
    __shared__ __align__(16) float Us[32][64];
    __shared__ float Ws[64][33];
    __shared__ float Cs[36][65];
    __shared__ float cws[DI*4];
    __shared__ float cbs[DI];
    __shared__ float dws[4][DI];
    __shared__ float dbs[DI];
    int dir = blockIdx.y;
    int t0 = blockIdx.x*64;
    int tid = threadIdx.x;
    int tg = tid & 15, eg = tid >> 4;
    {
        const float* cw = conv_w + (size_t)dir*DI*4;
        const float* cb = conv_b + dir*DI;
        const float* dw = dt_w + (size_t)dir*DI*4;
        const float* db = dt_b + dir*DI;
        for (int t=tid;t<DI*4;t+=256){ cws[t]=cw[t]; dws[t&3][t>>2]=dw[t]; }
        for (int t=tid;t<DI;t+=256){ cbs[t]=cb[t]; dbs[t]=db[t]; }
    }
    const float* xb = g_xzT[sl] + (size_t)dir*2*DI*NPIX;
    float* ub = g_u[sl] + (size_t)dir*DI*NPIX;
    const float* xp = xproj_w + (size_t)dir*36*DI;

    float acc[4][4];
#pragma unroll
    for (int j=0;j<4;j++){ acc[j][0]=0.f; acc[j][1]=0.f; acc[j][2]=0.f; acc[j][3]=0.f; }
    for (int k0=0;k0<DI;k0+=32){
        __syncthreads();
#pragma unroll
        for (int r=0;r<8;r++){
            int i = tid + r*256;
            int kk = i>>6, tt = i&63;
            int ch = k0+kk;
            int tok = t0+tt;
            int l = tok % Lseq;
            const float* row = xb + (size_t)ch*NPIX;
            float a = cbs[ch];
            if (dir==0){
#pragma unroll
                for (int j=0;j<4;j++) if (l>=j) a += row[tok-j]*cws[ch*4+3-j];
            } else {
#pragma unroll
                for (int j=0;j<4;j++) if (l+j<Lseq) a += row[tok+j]*cws[ch*4+3-j];
            }
            float uu = a/(1.f+__expf(-a));
            Us[kk][tt] = uu;
            ub[(size_t)ch*NPIX + tok] = uu;
        }
#pragma unroll
        for (int r=0;r<2;r++){
            int i = tid + r*256;
            int e = i>>3, kkb = (i&7)*4;
            float4 v = make_float4(0.f,0.f,0.f,0.f);
            if (e < 36) v = *(const float4*)&xp[(size_t)e*DI + k0+kkb];
            Ws[e][kkb+0]=v.x; Ws[e][kkb+1]=v.y; Ws[e][kkb+2]=v.z; Ws[e][kkb+3]=v.w;
        }
        __syncthreads();
#pragma unroll 8
        for (int kk=0;kk<32;kk++){
            float4 xv = *(const float4*)&Us[kk][tg*4];
#pragma unroll
            for (int j=0;j<4;j++){
                float wv = Ws[eg*4+j][kk];
                acc[j][0] += xv.x*wv; acc[j][1] += xv.y*wv;
                acc[j][2] += xv.z*wv; acc[j][3] += xv.w*wv;
            }
        }
    }
    __syncthreads();
    // stage valid rows to smem
#pragma unroll
    for (int j=0;j<4;j++){
        int n = eg*4 + j;
        if (n < 36){
#pragma unroll
            for (int mj=0;mj<4;mj++) Cs[n][tg*4+mj] = acc[j][mj];
        }
    }
    __syncthreads();
    // epilogue: 4 threads per token
    int tokl = tid & 63;
    int kg = tid >> 6;          // 0..3
    int tok = t0 + tokl;
    float d0 = Cs[0][tokl], d1 = Cs[1][tokl], d2 = Cs[2][tokl], d3 = Cs[3][tokl];
    float* dlb = g_dl[sl] + (size_t)dir*DI*NPIX;
#pragma unroll 8
    for (int c=0;c<32;c++){
        int ch = kg*32 + c;
        float t = dbs[ch] + dws[0][ch]*d0 + dws[1][ch]*d1 + dws[2][ch]*d2 + dws[3][ch]*d3;
        t = (t>20.f)? t : log1pf(__expf(t));
        dlb[(size_t)ch*NPIX + tok] = t;
    }
    size_t bo = ((size_t)dir*NPIX + tok)*DS;
    if (kg < 2){
#pragma unroll
        for (int i=0;i<8;i++) g_Bmb[sl][bo + kg*8 + i] = Cs[4 + kg*8 + i][tokl];
    } else {
#pragma unroll
        for (int i=0;i<8;i++) g_Cmb[sl][bo + (kg-2)*8 + i] = Cs[20 + (kg-2)*8 + i][tokl];
    }
}

// --------- GEMM2: acc[n][m] = sum_k W[wbase+n][k]*Xeff[xbase+k][m] ------------
// xmode 0: Xeff = X (+X2). xmode 2: Xeff[k][m]=relu(((m&31)==0?hub[k]:X[k][m])+bias[k])
// mode 0: C[n][m or M-1-m] = acc
// mode 1: C[n][pixmap(m)] = base[n][pixmap(m)] + acc
// mode 2: C[n][m] = C[n][m] + base[n][m] + acc
template<int TN>
__global__ __launch_bounds__(256) void k_gemm2(const float* __restrict__ X,
        const float* __restrict__ X2, const float* __restrict__ W,
        float* __restrict__ C, const float* __restrict__ base,
        const float* __restrict__ bias, const float* __restrict__ hub,
        int M, int K, int NW, int WS, int CS, int XS,
        int rev, int mode, int xmode)
{
    constexpr int BN = 16*TN;
    __shared__ __align__(16) float Xs[32][64];
    __shared__ float Ws[BN][33];
    int t0 = blockIdx.x*64;
    int wbase = blockIdx.y*WS;
    int cbase = blockIdx.y*CS;
    int xbase = blockIdx.y*XS;
    int tid = threadIdx.x;
    int tg = tid & 15, eg = tid >> 4;
    float acc[TN][4];
#pragma unroll
    for (int j=0;j<TN;j++){ acc[j][0]=0.f; acc[j][1]=0.f; acc[j][2]=0.f; acc[j][3]=0.f; }
    for (int k0=0;k0<K;k0+=32){
        if (xmode == 0){
#pragma unroll
            for (int r=0;r<2;r++){
                int i = tid + r*256;
                int kk = i>>4, tt = (i&15)*4;
                size_t gidx = (size_t)(xbase+k0+kk)*M + t0+tt;
                float4 v = *(const float4*)&X[gidx];
                if (X2){
                    float4 w = *(const float4*)&X2[gidx];
                    v.x+=w.x; v.y+=w.y; v.z+=w.z; v.w+=w.w;
                }
                *(float4*)&Xs[kk][tt] = v;
            }
        } else {
#pragma unroll
            for (int r=0;r<8;r++){
                int i = tid + r*256;
                int kk = i>>6, tt = i&63;
                int ch = k0+kk;
                int t = t0+tt;
                float v = ((t&31)==0) ? hub[ch] : X[(size_t)ch*M + t];
                Xs[kk][tt] = fmaxf(v + bias[ch], 0.f);
            }
        }
#pragma unroll
        for (int r=0;r<BN/32;r++){
            int i = tid + r*256;
            int e = i>>3, kkb = (i&7)*4;
            float4 v = make_float4(0.f,0.f,0.f,0.f);
            if (e < NW) v = *(const float4*)&W[(size_t)(wbase+e)*K + k0+kkb];
            Ws[e][kkb+0]=v.x; Ws[e][kkb+1]=v.y; Ws[e][kkb+2]=v.z; Ws[e][kkb+3]=v.w;
        }
        __syncthreads();
#pragma unroll 8
        for (int kk=0;kk<32;kk++){
            float4 xv = *(const float4*)&Xs[kk][tg*4];
#pragma unroll
            for (int j=0;j<TN;j++){
                float wv = Ws[eg*TN+j][kk];
                acc[j][0] += xv.x*wv; acc[j][1] += xv.y*wv;
                acc[j][2] += xv.z*wv; acc[j][3] += xv.w*wv;
            }
        }
        __syncthreads();
    }
#pragma unroll
    for (int j=0;j<TN;j++){
        size_t row = (size_t)(cbase + eg*TN + j)*M;
        if (mode == 0){
            if (!rev){
                float4 o = make_float4(acc[j][0],acc[j][1],acc[j][2],acc[j][3]);
                *(float4*)&C[row + t0 + tg*4] = o;
            } else {
#pragma unroll
                for (int mj=0;mj<4;mj++) C[row + (M-1-(t0+tg*4+mj))] = acc[j][mj];
            }
        } else if (mode == 1){
#pragma unroll
            for (int mj=0;mj<4;mj++){
                int p = pixmap(t0 + tg*4 + mj);
                C[row + p] = base[row + p] + acc[j][mj];
            }
        } else {
            size_t i = row + t0 + tg*4;
            float4 b = *(const float4*)&base[i];
            float4 c = *(const float4*)&C[i];
            c.x += b.x + acc[j][0]; c.y += b.y + acc[j][1];
            c.z += b.z + acc[j][2]; c.w += b.w + acc[j][3];
            *(float4*)&C[i] = c;
        }
    }
}

// --------- combined stage-1 window out-proj: yo (mode2) + nfx + nfy(rev) -----
__global__ __launch_bounds__(256) void k_out3(const float* __restrict__ X0,
        const float* __restrict__ X1, const float* __restrict__ Wa,
        const float* __restrict__ Wb, float* __restrict__ cur,
        const float* __restrict__ buf, float* __restrict__ nfx, float* __restrict__ nfy)
{
    __shared__ __align__(16) float Xs0[32][64];
    __shared__ __align__(16) float Xs1[32][64];
    __shared__ float Was[64][33];
    __shared__ float Wbs[64][33];
    int t0 = blockIdx.x*64;
    int tid = threadIdx.x;
    int tg = tid & 15, eg = tid >> 4;
    float a1[4][4], a2[4][4], a3[4][4];
#pragma unroll
    for (int j=0;j<4;j++)
#pragma unroll
        for (int mj=0;mj<4;mj++){ a1[j][mj]=0.f; a2[j][mj]=0.f; a3[j][mj]=0.f; }
    for (int k0=0;k0<DI;k0+=32){
#pragma unroll
        for (int r=0;r<2;r++){
            int i = tid + r*256;
            int kk = i>>4, tt = (i&15)*4;
            size_t gidx = (size_t)(k0+kk)*NPIX + t0+tt;
            *(float4*)&Xs0[kk][tt] = *(const float4*)&X0[gidx];
            *(float4*)&Xs1[kk][tt] = *(const float4*)&X1[gidx];
        }
#pragma unroll
        for (int r=0;r<2;r++){
            int i = tid + r*256;
            int e = i>>3, kkb = (i&7)*4;
            float4 va = *(const float4*)&Wa[(size_t)e*DI + k0+kkb];
            Was[e][kkb+0]=va.x; Was[e][kkb+1]=va.y; Was[e][kkb+2]=va.z; Was[e][kkb+3]=va.w;
            float4 vb = *(const float4*)&Wb[(size_t)e*DI + k0+kkb];
            Wbs[e][kkb+0]=vb.x; Wbs[e][kkb+1]=vb.y; Wbs[e][kkb+2]=vb.z; Wbs[e][kkb+3]=vb.w;
        }
        __syncthreads();
#pragma unroll 8
        for (int kk=0;kk<32;kk++){
            float4 x0 = *(const float4*)&Xs0[kk][tg*4];
            float4 x1 = *(const float4*)&Xs1[kk][tg*4];
#pragma unroll
            for (int j=0;j<4;j++){
                float wa = Was[eg*4+j][kk];
                float wb = Wbs[eg*4+j][kk];
                a1[j][0] += x0.x*wa; a1[j][1] += x0.y*wa; a1[j][2] += x0.z*wa; a1[j][3] += x0.w*wa;
                a2[j][0] += x1.x*wa; a2[j][1] += x1.y*wa; a2[j][2] += x1.z*wa; a2[j][3] += x1.w*wa;
                a3[j][0] += x1.x*wb; a3[j][1] += x1.y*wb; a3[j][2] += x1.z*wb; a3[j][3] += x1.w*wb;
            }
        }
        __syncthreads();
    }
#pragma unroll
    for (int j=0;j<4;j++){
        size_t row = (size_t)(eg*4+j)*NPIX;
        size_t i = row + t0 + tg*4;
        float4 b = *(const float4*)&buf[i];
        float4 c = *(const float4*)&cur[i];
        c.x += b.x + a1[j][0] + a2[j][0];
        c.y += b.y + a1[j][1] + a2[j][1];
        c.z += b.z + a1[j][2] + a2[j][2];
        c.w += b.w + a1[j][3] + a2[j][3];
        *(float4*)&cur[i] = c;
        float4 fx = make_float4(a1[j][0],a1[j][1],a1[j][2],a1[j][3]);
        *(float4*)&nfx[i] = fx;
#pragma unroll
        for (int mj=0;mj<4;mj++) nfy[row + (NPIX-1-(t0+tg*4+mj))] = a3[j][mj];
    }
}

// ---------------- pixel scan + fused gate ----------------
__global__ void k_scan_pix(const float* __restrict__ Alog, const float* __restrict__ Dv, int sl)
{
    int dir = blockIdx.z, seq = blockIdx.y;
    int n = threadIdx.x & 15;
    int d = blockIdx.x*16 + (threadIdx.x>>4);
    float Aa = -__expf(Alog[((size_t)dir*DI+d)*DS+n]);
    float Dd = Dv[dir*DI+d];
    const float* dlp = g_dl[sl] + ((size_t)dir*DI+d)*NPIX;
    const float* up  = g_u [sl] + ((size_t)dir*DI+d)*NPIX;
    const float* Bp  = g_Bmb[sl] + (size_t)dir*NPIX*DS;
    const float* Cp  = g_Cmb[sl] + (size_t)dir*NPIX*DS;
    const float* zp  = g_xzT[sl] + (((size_t)dir*2+1)*DI+d)*NPIX;
    float* gp = (dir ? g_gb1[sl] : g_gb0[sl]) + (size_t)d*NPIX;
    float h = 0.f;
    int s0 = seq*LPIX;
    for (int t=0;t<LPIX;t++){
        int tok = s0 + (dir ? (LPIX-1-t) : t);
        float dd = dlp[tok];
        float uu = up[tok];
        float a = __expf(dd*Aa);
        h = h*a + dd*uu*Bp[(size_t)tok*DS+n];
        float cc = h*Cp[(size_t)tok*DS+n];
        cc += __shfl_xor_sync(0xffffffffu, cc, 8);
        cc += __shfl_xor_sync(0xffffffffu, cc, 4);
        cc += __shfl_xor_sync(0xffffffffu, cc, 2);
        cc += __shfl_xor_sync(0xffffffffu, cc, 1);
        if (n==0){
            float z = zp[tok];
            gp[tok] = (cc + uu*Dd) * (z/(1.f+__expf(-z)));
        }
    }
}

// ---------------- window scan: 3-phase chunked linear recurrence -------------
__global__ void k_scan_win1(const float* __restrict__ Alog, int sl)
{
    int dir = blockIdx.z, chunk = blockIdx.y;
    int n = threadIdx.x & 15;
    int d = blockIdx.x*16 + (threadIdx.x>>4);
    float Aa = -__expf(Alog[((size_t)dir*DI+d)*DS+n]);
    const float* dlp = g_dl[sl] + ((size_t)dir*DI+d)*NPIX;
    const float* up  = g_u [sl] + ((size_t)dir*DI+d)*NPIX;
    const float* Bp  = g_Bmb[sl] + (size_t)dir*NPIX*DS;
    float h = 0.f, p = 1.f;
    int s0 = chunk*CLEN;
    for (int t=0;t<CLEN;t++){
        int s = s0+t;
        int tok = dir ? (NPIX-1-s) : s;
        float dd = dlp[tok];
        float a = __expf(dd*Aa);
        h = h*a + dd*up[tok]*Bp[(size_t)tok*DS+n];
        p *= a;
    }
    size_t idx = (((size_t)dir*DI+d)*DS+n)*NCHUNK + chunk;
    g_P[sl][idx]=p; g_He[sl][idx]=h;
}

__global__ void k_scan_win2(int sl)
{
    int idx = blockIdx.x*blockDim.x + threadIdx.x;
    if (idx >= 2*DI*DS) return;
    size_t base = (size_t)idx*NCHUNK;
    float h = 0.f;
    for (int c=0;c<NCHUNK;c++){
        g_Hsb[sl][base+c] = h;
        h = g_He[sl][base+c] + g_P[sl][base+c]*h;
    }
}

__global__ void k_scan_win3(const float* __restrict__ Alog, const float* __restrict__ Dv, int sl)
{
    int dir = blockIdx.z, chunk = blockIdx.y;
    int n = threadIdx.x & 15;
    int d = blockIdx.x*16 + (threadIdx.x>>4);
    float Aa = -__expf(Alog[((size_t)dir*DI+d)*DS+n]);
    float Dd = Dv[dir*DI+d];
    const float* dlp = g_dl[sl] + ((size_t)dir*DI+d)*NPIX;
    const float* up  = g_u [sl] + ((size_t)dir*DI+d)*NPIX;
    const float* Bp  = g_Bmb[sl] + (size_t)dir*NPIX*DS;
    const float* Cp  = g_Cmb[sl] + (size_t)dir*NPIX*DS;
    const float* zp  = g_xzT[sl] + (((size_t)dir*2+1)*DI+d)*NPIX;
    float* gp = (dir ? g_gb1[sl] : g_gb0[sl]) + (size_t)d*NPIX;
    float h = g_Hsb[sl][(((size_t)dir*DI+d)*DS+n)*NCHUNK + chunk];
    int s0 = chunk*CLEN;
    for (int t=0;t<CLEN;t++){
        int s = s0+t;
        int tok = dir ? (NPIX-1-s) : s;
        float dd = dlp[tok];
        float uu = up[tok];
        float a = __expf(dd*Aa);
        h = h*a + dd*uu*Bp[(size_t)tok*DS+n];
        float cc = h*Cp[(size_t)tok*DS+n];
        cc += __shfl_xor_sync(0xffffffffu, cc, 8);
        cc += __shfl_xor_sync(0xffffffffu, cc, 4);
        cc += __shfl_xor_sync(0xffffffffu, cc, 2);
        cc += __shfl_xor_sync(0xffffffffu, cc, 1);
        if (n==0){
            float z = zp[tok];
            gp[tok] = (cc + uu*Dd) * (z/(1.f+__expf(-z)));
        }
    }
}

// ---------------- misc ----------------
__global__ void k_transpose(const float* __restrict__ src, float* __restrict__ dst)
{
    int p = blockIdx.x*blockDim.x + threadIdx.x;
    if (p >= NPIX) return;
    int c = blockIdx.y;
    int h = p/HWD, w = p%HWD;
    dst[(size_t)c*NPIX+p] = src[(size_t)c*NPIX + w*HWD + h];
}

__global__ void k_hubmean(const float* __restrict__ X, float* __restrict__ hub)
{
    int f = blockIdx.x;
    __shared__ float sm[256];
    float s = 0.f;
    for (int k=threadIdx.x;k<450;k+=256) s += X[(size_t)f*NPIX + k*32];
    sm[threadIdx.x]=s; __syncthreads();
    for (int st=128;st>0;st>>=1){
        if (threadIdx.x<st) sm[threadIdx.x]+=sm[threadIdx.x+st];
        __syncthreads();
    }
    if (threadIdx.x==0) hub[f]=sm[0]*(1.f/450.f);
}

__global__ void k_final(const float* __restrict__ x, const float* __restrict__ b2,
                        float* __restrict__ out)
{
    int p = blockIdx.x*blockDim.x + threadIdx.x;
    if (p >= NPIX) return;
    int c = blockIdx.y;
    int h = p/HWD, w = p%HWD;
    float g = ((p&31)==0 ? g_hub2[c] : g_t2[(size_t)c*NPIX+p]) + b2[c];
    out[(size_t)c*NPIX+p] = x[(size_t)c*NPIX+p] + g_cur[0][(size_t)c*NPIX+p]
        + g_cur[1][(size_t)c*NPIX + w*HWD + h] + g;
}

// ---------------- host driver ----------------
struct Ptrs {
    float *xzT, *gb0, *gb1, *cur, *buf;
};

static void mamba_inv(cudaStream_t st, const Ptrs& P, int sl,
    const float* img, int pixelMode, int i,
    const float* in_w_all, const float* conv_w_all, const float* conv_b_all,
    const float* xproj_all, const float* dt_w_all, const float* dt_b_all,
    const float* Alog_all, const float* D_all,
    const float* lng, const float* lnb)
{
    const float* in_w   = in_w_all   + (size_t)i*2*2*DI*CM;
    const float* conv_w = conv_w_all + (size_t)i*2*DI*4;
    const float* conv_b = conv_b_all + (size_t)i*2*DI;
    const float* xproj  = xproj_all  + (size_t)i*2*36*DI;
    const float* dt_w   = dt_w_all   + (size_t)i*2*DI*4;
    const float* dt_b   = dt_b_all   + (size_t)i*2*DI;
    const float* Alog   = Alog_all   + (size_t)i*2*DI*DS;
    const float* Dv     = D_all      + (size_t)i*2*DI;
    const float* lg     = lng + (size_t)i*CM;
    const float* lb     = lnb + (size_t)i*CM;

    k_inproj<<<dim3(225,4),256,0,st>>>(img, in_w, P.xzT, lg, lb, pixelMode);
    k_cxp<<<dim3(225,2),256,0,st>>>(conv_w, conv_b, xproj, dt_w, dt_b,
                                    pixelMode?LPIX:NPIX, sl);
    if (pixelMode){
        k_scan_pix<<<dim3(8,25,2),256,0,st>>>(Alog, Dv, sl);
    } else {
        k_scan_win1<<<dim3(8,NCHUNK,2),256,0,st>>>(Alog, sl);
        k_scan_win2<<<4,1024,0,st>>>(sl);
        k_scan_win3<<<dim3(8,NCHUNK,2),256,0,st>>>(Alog, Dv, sl);
    }
}

extern "C" void kernel_launch(void* const* d_in, const int* in_sizes, int n_in,
                              void* d_out, int out_size)
{
    const float* A[28];
    if (in_sizes[9] == 256){
        const int map[28] = {0,1,2,3,4,5,6,7,8, 11,12,13,14,15,16,17,18,
                             9,10, 19,20, 21,22,23,24,25,26,27};
        for (int k=0;k<28;k++) A[k]=(const float*)d_in[map[k]];
    } else {
        for (int k=0;k<28;k++) A[k]=(const float*)d_in[k];
    }
    const float* x = A[0];

    static cudaStream_t s[2] = {nullptr, nullptr};
    static cudaEvent_t evFork = nullptr, evJoin0 = nullptr, evJoin1 = nullptr;
    if (!s[0]){
        cudaStreamCreateWithFlags(&s[0], cudaStreamNonBlocking);
        cudaStreamCreateWithFlags(&s[1], cudaStreamNonBlocking);
        cudaEventCreateWithFlags(&evFork,  cudaEventDisableTiming);
        cudaEventCreateWithFlags(&evJoin0, cudaEventDisableTiming);
        cudaEventCreateWithFlags(&evJoin1, cudaEventDisableTiming);
    }

    Ptrs P[2];
    float *p_nf, *p_t1, *p_t2, *p_hub1, *p_hub2;
    {
        float* q;
        cudaGetSymbolAddress((void**)&q, g_xzT);  P[0].xzT = q; P[1].xzT = q + (size_t)2*2*DI*NPIX;
        cudaGetSymbolAddress((void**)&q, g_gb0);  P[0].gb0 = q; P[1].gb0 = q + (size_t)DI*NPIX;
        cudaGetSymbolAddress((void**)&q, g_gb1);  P[0].gb1 = q; P[1].gb1 = q + (size_t)DI*NPIX;
        cudaGetSymbolAddress((void**)&q, g_cur);  P[0].cur = q; P[1].cur = q + (size_t)CM*NPIX;
        cudaGetSymbolAddress((void**)&q, g_buf);  P[0].buf = q; P[1].buf = q + (size_t)CM*NPIX;
        cudaGetSymbolAddress((void**)&p_nf, g_nf);
        cudaGetSymbolAddress((void**)&p_t1, g_t1);
        cudaGetSymbolAddress((void**)&p_t2, g_t2);
        cudaGetSymbolAddress((void**)&p_hub1, g_hub1);
        cudaGetSymbolAddress((void**)&p_hub2, g_hub2);
    }

    cudaEventRecord(evFork, 0);
    cudaStreamWaitEvent(s[0], evFork, 0);
    cudaStreamWaitEvent(s[1], evFork, 0);

    auto run_branch = [&](int sl, int base, float* nfx, float* nfy){
        cudaStream_t st = s[sl];
        const Ptrs& Q = P[sl];
        for (int sstage=0; sstage<2; sstage++){
            int i = base+sstage;
            // pixel mamba on cur
            mamba_inv(st, Q, sl, Q.cur, 1, i, A[1],A[2],A[3],A[4],A[5],A[6],A[7],A[8],
                      A[17],A[18]);
            // buf = cur + pixel residual (scatter epilogue)
            k_gemm2<4><<<dim3(225,1),256,0,st>>>(Q.gb0, Q.gb1, A[21] + (size_t)i*CM*DI,
                                                 Q.buf, Q.cur, nullptr, nullptr,
                                                 NPIX, DI, 64, 64, 64, 0, 0, 1, 0);
            // window mamba on buf
            mamba_inv(st, Q, sl, Q.buf, 0, i, A[9],A[10],A[11],A[12],A[13],A[14],A[15],A[16],
                      A[19],A[20]);
            if (sstage==1){
                k_out3<<<225,256,0,st>>>(Q.gb0, Q.gb1,
                                         A[22] + (size_t)i*CM*DI, A[23] + (size_t)i*CM*DI,
                                         Q.cur, Q.buf, nfx, nfy);
            } else {
                k_gemm2<4><<<dim3(225,1),256,0,st>>>(Q.gb0, Q.gb1, A[22] + (size_t)i*CM*DI,
                                                     Q.cur, Q.buf, nullptr, nullptr,
                                                     NPIX, DI, 64, 64, 64, 0, 0, 2, 0);
            }
        }
    };

    cudaMemcpyAsync(P[0].cur, x, sizeof(float)*CM*NPIX, cudaMemcpyDeviceToDevice, s[0]);
    run_branch(0, 0, p_nf + 0*(size_t)CM*NPIX, p_nf + 1*(size_t)CM*NPIX);

    k_transpose<<<dim3(113,CM),128,0,s[1]>>>(x, P[1].cur);
    run_branch(1, 2, p_nf + 2*(size_t)CM*NPIX, p_nf + 3*(size_t)CM*NPIX);

    cudaEventRecord(evJoin0, s[0]);
    cudaEventRecord(evJoin1, s[1]);
    cudaStreamWaitEvent(0, evJoin0, 0);
    cudaStreamWaitEvent(0, evJoin1, 0);

    // GCN: layer 1 (256 -> 128), raw t1
    k_gemm2<8><<<dim3(225,1),256>>>(p_nf, nullptr, A[24], p_t1, nullptr, nullptr, nullptr,
                                    NPIX, 4*CM, 128, 128, 128, 0, 0, 0, 0);
    k_hubmean<<<2*CM,256>>>(p_t1, p_hub1);
    // layer 2 (128 -> 64) with fused hub-substitute + bias + relu on load
    k_gemm2<4><<<dim3(225,1),256>>>(p_t1, nullptr, A[26], p_t2, nullptr, A[25], p_hub1,
                                    NPIX, 2*CM, 64, 64, 64, 0, 0, 0, 2);
    k_hubmean<<<CM,256>>>(p_t2, p_hub2);
    // final: gcn(hub+bias fused) + old + lastx + lastx_T^T
    k_final<<<dim3(113,CM),128>>>(x, A[27], (float*)d_out);
}